// round 13
// baseline (speedup 1.0000x reference)
#include <cuda_runtime.h>
#include <cuda_bf16.h>
#include <cuda_fp16.h>
#include <cstdint>

#define N_NODES  50000
#define N_EDGES  800000
#define HID      128
#define EDGE_D   16
#define N_GRAPHS 64

#define ETILE 128
#define NTILE 32
#define NUM_ETILES (N_EDGES / ETILE)
#define NUM_PTILES ((N_NODES + 31) / 32)
#define EGRID 304
#define PGRID 152

// ---------------- device scratch (static, no allocation) ----------------
__device__ float g_hAB[(size_t)N_NODES * 256];   // hA | hB  (51.2 MB)
__device__ float g_hn1[(size_t)N_NODES * 128];   // h @ Wn1a + bn1 (25.6 MB)
__device__ float g_agg[(size_t)N_NODES * HID];   // scatter target (25.6 MB)
__device__ float g_pool[N_GRAPHS * HID];         // sum of h per graph
__device__ float g_poolm[N_GRAPHS * HID];        // sum of mid per graph
__device__ float g_cnt[N_GRAPHS];
__device__ int   g_row[N_EDGES];
__device__ int   g_col[N_EDGES];
__device__ int   g_batch[N_NODES];
__device__ int   g_is64;

__device__ __forceinline__ float silu_f(float v) {
    return __fdividef(v, 1.0f + __expf(-v));
}

// bf16 mma m16n8k16 (k_pre)
__device__ __forceinline__ void mma_bf16(float* d, uint32_t a0, uint32_t a1,
                                         uint32_t a2, uint32_t a3,
                                         uint32_t b0, uint32_t b1) {
    asm volatile(
        "mma.sync.aligned.m16n8k16.row.col.f32.bf16.bf16.f32 "
        "{%0,%1,%2,%3}, {%4,%5,%6,%7}, {%8,%9}, {%0,%1,%2,%3};"
        : "+f"(d[0]), "+f"(d[1]), "+f"(d[2]), "+f"(d[3])
        : "r"(a0), "r"(a1), "r"(a2), "r"(a3), "r"(b0), "r"(b1));
}

// fp16 mma m16n8k16 (k_edge)
__device__ __forceinline__ void mma_f16(float* d, uint32_t a0, uint32_t a1,
                                        uint32_t a2, uint32_t a3,
                                        uint32_t b0, uint32_t b1) {
    asm volatile(
        "mma.sync.aligned.m16n8k16.row.col.f32.f16.f16.f32 "
        "{%0,%1,%2,%3}, {%4,%5,%6,%7}, {%8,%9}, {%0,%1,%2,%3};"
        : "+f"(d[0]), "+f"(d[1]), "+f"(d[2]), "+f"(d[3])
        : "r"(a0), "r"(a1), "r"(a2), "r"(a3), "r"(b0), "r"(b1));
}

__device__ __forceinline__ void ldsm4(uint32_t* r, uint32_t addr) {
    asm volatile("ldmatrix.sync.aligned.m8n8.x4.shared.b16 {%0,%1,%2,%3}, [%4];"
                 : "=r"(r[0]), "=r"(r[1]), "=r"(r[2]), "=r"(r[3]) : "r"(addr));
}

__device__ __forceinline__ uint2 pack_hi4(float a, float b, float c, float d,
                                          float& ra, float& rb, float& rc, float& rd) {
    const __nv_bfloat16 ha = __float2bfloat16(a);
    const __nv_bfloat16 hb = __float2bfloat16(b);
    const __nv_bfloat16 hc = __float2bfloat16(c);
    const __nv_bfloat16 hd = __float2bfloat16(d);
    ra = a - __bfloat162float(ha);
    rb = b - __bfloat162float(hb);
    rc = c - __bfloat162float(hc);
    rd = d - __bfloat162float(hd);
    __nv_bfloat162 p0; p0.x = ha; p0.y = hb;
    __nv_bfloat162 p1; p1.x = hc; p1.y = hd;
    uint2 r;
    r.x = *reinterpret_cast<uint32_t*>(&p0);
    r.y = *reinterpret_cast<uint32_t*>(&p1);
    return r;
}
__device__ __forceinline__ uint2 pack_bf4(float a, float b, float c, float d) {
    __nv_bfloat162 p0; p0.x = __float2bfloat16(a); p0.y = __float2bfloat16(b);
    __nv_bfloat162 p1; p1.x = __float2bfloat16(c); p1.y = __float2bfloat16(d);
    uint2 r;
    r.x = *reinterpret_cast<uint32_t*>(&p0);
    r.y = *reinterpret_cast<uint32_t*>(&p1);
    return r;
}
// fp16 packers (k_edge)
__device__ __forceinline__ uint2 pack_h4(float a, float b, float c, float d) {
    __half2 p0 = __floats2half2_rn(a, b);
    __half2 p1 = __floats2half2_rn(c, d);
    uint2 r;
    r.x = *reinterpret_cast<uint32_t*>(&p0);
    r.y = *reinterpret_cast<uint32_t*>(&p1);
    return r;
}

// ---------------- init (launch #1) ----------------
__global__ void k_init(const void* __restrict__ ei) {
    const int i = blockIdx.x * blockDim.x + threadIdx.x;
    if (i < (N_NODES * HID) / 4)
        reinterpret_cast<float4*>(g_agg)[i] = make_float4(0.f, 0.f, 0.f, 0.f);
    if (i < N_GRAPHS * HID) { g_pool[i] = 0.f; g_poolm[i] = 0.f; }
    if (i < N_GRAPHS)       g_cnt[i] = 0.f;
    if (i == 0) {
        const unsigned int* p = (const unsigned int*)ei;
        int is64 = 1;
        for (int j = 0; j < 16; j++) if (p[2 * j + 1] != 0u) is64 = 0;
        g_is64 = is64;
    }
}

// ---------------- index conversion (launch #2) ----------------
__global__ void k_cvt_idx(const void* __restrict__ ei, const void* __restrict__ batch) {
    const int i = blockIdx.x * blockDim.x + threadIdx.x;
    const bool is64 = (g_is64 != 0);
    if (i < N_EDGES) {
        if (is64) {
            const long long* p = (const long long*)ei;
            g_row[i] = (int)p[i];
            g_col[i] = (int)p[N_EDGES + i];
        } else {
            const int* p = (const int*)ei;
            g_row[i] = p[i];
            g_col[i] = p[N_EDGES + i];
        }
    }
    if (i < N_NODES) {
        if (is64) g_batch[i] = (int)((const long long*)batch)[i];
        else      g_batch[i] = ((const int*)batch)[i];
    }
}

// ---------------- k_pre (launch #3): persistent bf16 3-term pre-GEMM ----------------
#define BSTRIDE 136   // b16 elements per row (272 B) -> conflict-free fragments

#define PB_BH   0                  // 384x136 bf16 hi = 104448 B
#define PB_BL   104448             // 104448 B
#define PB_AH   208896             // 32x136 bf16 hi = 8704 B
#define PB_AL   217600             // 8704 B
#define PB_BIAS 226304             // 384 f32 = 1536 B
#define PRE_SMEM_BYTES 227840

__global__ __launch_bounds__(512, 1) void k_pre(const float* __restrict__ h,
                                                const float* __restrict__ We1,
                                                const float* __restrict__ be1,
                                                const float* __restrict__ Wn1,
                                                const float* __restrict__ bn1) {
    extern __shared__ char smem[];
    __nv_bfloat16* Bh = reinterpret_cast<__nv_bfloat16*>(smem + PB_BH);
    __nv_bfloat16* Bl = reinterpret_cast<__nv_bfloat16*>(smem + PB_BL);
    __nv_bfloat16* Ah = reinterpret_cast<__nv_bfloat16*>(smem + PB_AH);
    __nv_bfloat16* Al = reinterpret_cast<__nv_bfloat16*>(smem + PB_AL);
    float* bias_s = reinterpret_cast<float*>(smem + PB_BIAS);

    const int t = threadIdx.x;
    const int w = t >> 5, lane = t & 31;

    for (int i = t; i < 384 * 128; i += 512) {
        const int c = i >> 7, k = i & 127;
        float v;
        if (c < 128)       v = We1[k * 128 + c];
        else if (c < 256)  v = We1[(128 + k) * 128 + (c - 128)];
        else               v = Wn1[k * 128 + (c - 256)];
        const __nv_bfloat16 hi = __float2bfloat16(v);
        Bh[c * BSTRIDE + k] = hi;
        Bl[c * BSTRIDE + k] = __float2bfloat16(v - __bfloat162float(hi));
    }
    for (int i = t; i < 384; i += 512) {
        float b = 0.f;
        if (i < 128)      b = be1[i];
        else if (i >= 256) b = bn1[i - 256];
        bias_s[i] = b;
    }
    __syncthreads();

    const int mt = w & 1;
    const int nb = w >> 1;
    const int g  = lane >> 2;
    const int tq = lane & 3;

    for (int tile = blockIdx.x; tile < NUM_PTILES; tile += PGRID) {
        const int n0 = tile * 32;
        __syncthreads();
        for (int idx = t; idx < 1024; idx += 512) {
            const int n = idx >> 5, kq = idx & 31;
            float4 v = make_float4(0.f, 0.f, 0.f, 0.f);
            if (n0 + n < N_NODES)
                v = *reinterpret_cast<const float4*>(h + (size_t)(n0 + n) * 128 + kq * 4);
            float la, lb, lc, ld;
            const uint2 hv = pack_hi4(v.x, v.y, v.z, v.w, la, lb, lc, ld);
            *reinterpret_cast<uint2*>(Ah + n * BSTRIDE + kq * 4) = hv;
            *reinterpret_cast<uint2*>(Al + n * BSTRIDE + kq * 4) = pack_bf4(la, lb, lc, ld);
        }
        __syncthreads();

        float d[6][4];
#pragma unroll
        for (int nt = 0; nt < 6; nt++)
#pragma unroll
            for (int j = 0; j < 4; j++) d[nt][j] = 0.f;

        const int arow = mt * 16 + g;
#pragma unroll
        for (int ks = 0; ks < 8; ks++) {
            const int kb = ks * 16;
            const __nv_bfloat16* Ap = Ah + arow * BSTRIDE + 2 * tq + kb;
            const uint32_t a0 = *reinterpret_cast<const uint32_t*>(Ap);
            const uint32_t a1 = *reinterpret_cast<const uint32_t*>(Ap + 8 * BSTRIDE);
            const uint32_t a2 = *reinterpret_cast<const uint32_t*>(Ap + 8);
            const uint32_t a3 = *reinterpret_cast<const uint32_t*>(Ap + 8 * BSTRIDE + 8);
            const __nv_bfloat16* Lp = Al + arow * BSTRIDE + 2 * tq + kb;
            const uint32_t l0 = *reinterpret_cast<const uint32_t*>(Lp);
            const uint32_t l1 = *reinterpret_cast<const uint32_t*>(Lp + 8 * BSTRIDE);
            const uint32_t l2 = *reinterpret_cast<const uint32_t*>(Lp + 8);
            const uint32_t l3 = *reinterpret_cast<const uint32_t*>(Lp + 8 * BSTRIDE + 8);
            uint32_t bf[6][2];
#pragma unroll
            for (int nt = 0; nt < 6; nt++) {
                const __nv_bfloat16* Bp = Bh + (nb * 48 + nt * 8 + g) * BSTRIDE + 2 * tq + kb;
                bf[nt][0] = *reinterpret_cast<const uint32_t*>(Bp);
                bf[nt][1] = *reinterpret_cast<const uint32_t*>(Bp + 8);
            }
#pragma unroll
            for (int nt = 0; nt < 6; nt++) {
                mma_bf16(d[nt], a0, a1, a2, a3, bf[nt][0], bf[nt][1]);
                mma_bf16(d[nt], l0, l1, l2, l3, bf[nt][0], bf[nt][1]);
            }
#pragma unroll
            for (int nt = 0; nt < 6; nt++) {
                const __nv_bfloat16* Bp = Bl + (nb * 48 + nt * 8 + g) * BSTRIDE + 2 * tq + kb;
                bf[nt][0] = *reinterpret_cast<const uint32_t*>(Bp);
                bf[nt][1] = *reinterpret_cast<const uint32_t*>(Bp + 8);
            }
#pragma unroll
            for (int nt = 0; nt < 6; nt++)
                mma_bf16(d[nt], a0, a1, a2, a3, bf[nt][0], bf[nt][1]);
        }

        const int r0 = n0 + mt * 16 + g;
        const int r1 = r0 + 8;
#pragma unroll
        for (int nt = 0; nt < 6; nt++) {
            const int col = nb * 48 + nt * 8 + 2 * tq;
            const float b0 = bias_s[col], b1 = bias_s[col + 1];
            float2 v0 = make_float2(d[nt][0] + b0, d[nt][1] + b1);
            float2 v1 = make_float2(d[nt][2] + b0, d[nt][3] + b1);
            if (col < 256) {
                if (r0 < N_NODES) *reinterpret_cast<float2*>(g_hAB + (size_t)r0 * 256 + col) = v0;
                if (r1 < N_NODES) *reinterpret_cast<float2*>(g_hAB + (size_t)r1 * 256 + col) = v1;
            } else {
                if (r0 < N_NODES) *reinterpret_cast<float2*>(g_hn1 + (size_t)r0 * 128 + col - 256) = v0;
                if (r1 < N_NODES) *reinterpret_cast<float2*>(g_hn1 + (size_t)r1 * 128 + col - 256) = v1;
            }
        }
    }
}

// ---------------- fused edge kernel (launch #4; 2 CTAs/SM, ETILE=128, fp16 2-term) ----
#define SB_W2H   0                 // 128x136 fp16 = 34816 B (W2^T hi only)
#define SB_UH    34816             // 34816 B  u hi (fp16)
#define SB_UL    69632             // 34816 B  u lo (fp16)
#define SB_W1E   104448            // 2048 f32 = 8192 B
#define SB_W1R   112640            // 512 B
#define SB_BE2   113152            // 512 B
#define EDGE_SMEM_BYTES 113664

__global__ __launch_bounds__(512, 2) void k_edge(const float* __restrict__ x,
                                                 const float* __restrict__ ea,
                                                 const float* __restrict__ We1,
                                                 const float* __restrict__ We2,
                                                 const float* __restrict__ be2) {
    extern __shared__ char smem[];
    __half* w2h = reinterpret_cast<__half*>(smem + SB_W2H);
    __half* uhi = reinterpret_cast<__half*>(smem + SB_UH);
    __half* ulo = reinterpret_cast<__half*>(smem + SB_UL);
    float* W1e_s = reinterpret_cast<float*>(smem + SB_W1E);
    float* W1r_s = reinterpret_cast<float*>(smem + SB_W1R);
    float* be2_s = reinterpret_cast<float*>(smem + SB_BE2);

    const int t = threadIdx.x;
    const int w = t >> 5, lane = t & 31;

    // stage W2^T fp16 (once per block): We2 is [k][c] -> w2h[c][k]
    for (int i = t; i < 16384; i += 512) {
        const int k = i >> 7, c = i & 127;
        w2h[c * BSTRIDE + k] = __float2half_rn(We2[i]);
    }
    for (int i = t; i < 2048; i += 512) W1e_s[i] = We1[257 * 128 + i];
    if (t < 128) {
        W1r_s[t] = We1[256 * 128 + t];
        be2_s[t] = be2[t];
    }
    __syncthreads();

    const float4 wr = *reinterpret_cast<const float4*>(W1r_s + lane * 4);

    // Phase-B tiling: 16 warps -> m16 (mt = w&7) x n64 (nh = w>>3)
    const int mt = w & 7;
    const int nh = w >> 3;
    const int g  = lane >> 2;
    const int tq = lane & 3;

    // ldmatrix lane maps
    const int rA = lane & 15;
    const int kA = (lane & 16) ? 8 : 0;
    const int rB = ((lane >> 4) & 1) * 8 + (lane & 7);
    const int kB = (lane & 8) ? 8 : 0;
    const uint32_t uhi_s = (uint32_t)__cvta_generic_to_shared(uhi);
    const uint32_t ulo_s = (uint32_t)__cvta_generic_to_shared(ulo);
    const uint32_t w2h_s = (uint32_t)__cvta_generic_to_shared(w2h);
    const uint32_t aoff  = (uint32_t)(((mt * 16 + rA) * BSTRIDE + kA) * 2);
    uint32_t boff[2][2];
#pragma unroll
    for (int hf = 0; hf < 2; hf++)
#pragma unroll
        for (int p = 0; p < 2; p++)
            boff[hf][p] = (uint32_t)(((nh * 64 + hf * 32 + p * 16 + rB) * BSTRIDE + kB) * 2);

    for (int tile = blockIdx.x; tile < NUM_ETILES; tile += EGRID) {
        const int e0 = tile * ETILE;
        __syncthreads();   // protect u buffers vs previous tile readers

        // ---- Phase A: 16 warps x 8 edges; u split hi/lo (fp16) -> smem
        {
            const int ebase = w * 8;
            const int co    = lane * 4;
            int r8 = 0, c8 = 0;
            float rad8 = 0.f;
            if (lane < 8) {
                const int eg = e0 + ebase + lane;
                r8 = g_row[eg];
                c8 = g_col[eg];
                const float dx = x[r8 * 3 + 0] - x[c8 * 3 + 0];
                const float dy = x[r8 * 3 + 1] - x[c8 * 3 + 1];
                const float dz = x[r8 * 3 + 2] - x[c8 * 3 + 2];
                rad8 = dx * dx + dy * dy + dz * dz;
            }
            float acc[8][4];
#pragma unroll
            for (int ii = 0; ii < 8; ii++) {
                const int r   = __shfl_sync(0xffffffffu, r8, ii);
                const int c   = __shfl_sync(0xffffffffu, c8, ii);
                const float rad = __shfl_sync(0xffffffffu, rad8, ii);
                const float4 a4 = *reinterpret_cast<const float4*>(g_hAB + (size_t)r * 256 + co);
                const float4 b4 = *reinterpret_cast<const float4*>(g_hAB + (size_t)c * 256 + 128 + co);
                acc[ii][0] = fmaf(rad, wr.x, a4.x + b4.x);
                acc[ii][1] = fmaf(rad, wr.y, a4.y + b4.y);
                acc[ii][2] = fmaf(rad, wr.z, a4.z + b4.z);
                acc[ii][3] = fmaf(rad, wr.w, a4.w + b4.w);
            }
#pragma unroll
            for (int jb = 0; jb < 4; jb++) {
                float4 wv[4];
#pragma unroll
                for (int q = 0; q < 4; q++)
                    wv[q] = *reinterpret_cast<const float4*>(W1e_s + (jb * 4 + q) * 128 + co);
#pragma unroll
                for (int ii = 0; ii < 8; ii++) {
                    const float4 e4 = __ldg(reinterpret_cast<const float4*>(
                        ea + (size_t)(e0 + w * 8 + ii) * 16 + jb * 4));
                    const float ev[4] = {e4.x, e4.y, e4.z, e4.w};
#pragma unroll
                    for (int q = 0; q < 4; q++) {
                        acc[ii][0] = fmaf(ev[q], wv[q].x, acc[ii][0]);
                        acc[ii][1] = fmaf(ev[q], wv[q].y, acc[ii][1]);
                        acc[ii][2] = fmaf(ev[q], wv[q].z, acc[ii][2]);
                        acc[ii][3] = fmaf(ev[q], wv[q].w, acc[ii][3]);
                    }
                }
            }
#pragma unroll
            for (int ii = 0; ii < 8; ii++) {
                const int e = ebase + ii;
                const float sx = silu_f(acc[ii][0]), sy = silu_f(acc[ii][1]);
                const float sz = silu_f(acc[ii][2]), sw = silu_f(acc[ii][3]);
                const __half hx = __float2half_rn(sx);
                const __half hy = __float2half_rn(sy);
                const __half hz = __float2half_rn(sz);
                const __half hw = __float2half_rn(sw);
                __half2 hp0; hp0.x = hx; hp0.y = hy;
                __half2 hp1; hp1.x = hz; hp1.y = hw;
                uint2 hv;
                hv.x = *reinterpret_cast<uint32_t*>(&hp0);
                hv.y = *reinterpret_cast<uint32_t*>(&hp1);
                *reinterpret_cast<uint2*>(uhi + e * BSTRIDE + co) = hv;
                *reinterpret_cast<uint2*>(ulo + e * BSTRIDE + co) =
                    pack_h4(sx - __half2float(hx), sy - __half2float(hy),
                            sz - __half2float(hz), sw - __half2float(hw));
            }
        }
        __syncthreads();

        // ---- Phase B: D = u_hi@W_hi + u_lo@W_hi (fp16, LDSM + mma)
        {
            float d[8][4];
#pragma unroll
            for (int nt = 0; nt < 8; nt++)
#pragma unroll
                for (int j = 0; j < 4; j++) d[nt][j] = 0.f;

#pragma unroll
            for (int ks = 0; ks < 8; ks++) {
                const uint32_t kb2 = ks * 32;
                uint32_t ah[4], al[4];
                ldsm4(ah, uhi_s + aoff + kb2);
                ldsm4(al, ulo_s + aoff + kb2);
#pragma unroll
                for (int hf = 0; hf < 2; hf++) {
                    uint32_t bf[2][4];
                    ldsm4(bf[0], w2h_s + boff[hf][0] + kb2);
                    ldsm4(bf[1], w2h_s + boff[hf][1] + kb2);
#pragma unroll
                    for (int p = 0; p < 2; p++)
#pragma unroll
                        for (int sub = 0; sub < 2; sub++) {
                            const int nt = hf * 4 + p * 2 + sub;
                            const uint32_t b0 = bf[p][sub * 2], b1 = bf[p][sub * 2 + 1];
                            mma_f16(d[nt], ah[0], ah[1], ah[2], ah[3], b0, b1);
                            mma_f16(d[nt], al[0], al[1], al[2], al[3], b0, b1);
                        }
                }
            }

            // epilogue: silu(+bias), shfl-pair, red.v4 scatter
            const int er0 = g_row[e0 + mt * 16 + g];
            const int er1 = g_row[e0 + mt * 16 + g + 8];
            const bool evenq = (tq & 1) == 0;
#pragma unroll
            for (int nt = 0; nt < 8; nt++) {
                const int col = nh * 64 + nt * 8 + 2 * tq;
                const float b0v = be2_s[col];
                const float b1v = be2_s[col + 1];
                const float v00 = silu_f(d[nt][0] + b0v);
                const float v01 = silu_f(d[nt][1] + b1v);
                const float v10 = silu_f(d[nt][2] + b0v);
                const float v11 = silu_f(d[nt][3] + b1v);
                const float p00 = __shfl_xor_sync(0xffffffffu, v00, 1);
                const float p01 = __shfl_xor_sync(0xffffffffu, v01, 1);
                const float p10 = __shfl_xor_sync(0xffffffffu, v10, 1);
                const float p11 = __shfl_xor_sync(0xffffffffu, v11, 1);
                const int colbase = nh * 64 + nt * 8 + (tq & 2) * 2;
                if (evenq) {
                    asm volatile("red.global.add.v4.f32 [%0], {%1, %2, %3, %4};"
                                 :: "l"(g_agg + (size_t)er0 * 128 + colbase),
                                    "f"(v00), "f"(v01), "f"(p00), "f"(p01) : "memory");
                } else {
                    asm volatile("red.global.add.v4.f32 [%0], {%1, %2, %3, %4};"
                                 :: "l"(g_agg + (size_t)er1 * 128 + colbase),
                                    "f"(p10), "f"(p11), "f"(v10), "f"(v11) : "memory");
                }
            }
        }
    }
}

// ---------------- k_node (launch #5): mid = silu(hn1 + agg@Wn1b); scatter to pools ----
#define NODE_SMEM_FLOATS (128 * 36 + 32)
#define NODE_SMEM_BYTES  (NODE_SMEM_FLOATS * 4)

__global__ __launch_bounds__(256) void k_node(const float* __restrict__ h,
                                              const float* __restrict__ Wn1) {
    extern __shared__ float sm[];
    float* a_s = sm;
    int*   b_s = reinterpret_cast<int*>(sm + 128 * 36);

    const int n0 = blockIdx.x * NTILE;
    const int t = threadIdx.x;
    {
        const int n  = t >> 3;
        const int k4 = t & 7;
        const int ng = n0 + n;
#pragma unroll
        for (int j = 0; j < 4; j++) {
            const int k = k4 * 16 + j * 4;
            float4 w = make_float4(0.f, 0.f, 0.f, 0.f);
            if (ng < N_NODES)
                w = *reinterpret_cast<const float4*>(g_agg + (size_t)ng * 128 + k);
            a_s[(k + 0) * 36 + n] = w.x;
            a_s[(k + 1) * 36 + n] = w.y;
            a_s[(k + 2) * 36 + n] = w.z;
            a_s[(k + 3) * 36 + n] = w.w;
        }
        if (t < 32) b_s[t] = (n0 + t < N_NODES) ? g_batch[n0 + t] : 0;
    }
    __syncthreads();

    const int cg = t & 31;
    const int ng = t >> 5;
    const int cn = cg * 4;
    float acc[4][4];
#pragma unroll
    for (int i = 0; i < 4; i++)
#pragma unroll
        for (int j = 0; j < 4; j++) acc[i][j] = 0.f;

    for (int k = 0; k < 128; k++) {
        float av[4];
#pragma unroll
        for (int i = 0; i < 4; i++) av[i] = a_s[k * 36 + ng * 4 + i];
        const float4 w = __ldg(reinterpret_cast<const float4*>(Wn1 + (128 + k) * 128 + cn));
        const float wv[4] = {w.x, w.y, w.z, w.w};
#pragma unroll
        for (int i = 0; i < 4; i++)
#pragma unroll
            for (int j = 0; j < 4; j++) acc[i][j] = fmaf(av[i], wv[j], acc[i][j]);
    }
#pragma unroll
    for (int i = 0; i < 4; i++) {
        const int n = n0 + ng * 4 + i;
        if (n < N_NODES) {
            const int b = b_s[ng * 4 + i];
            const float4 hn = *reinterpret_cast<const float4*>(g_hn1 + (size_t)n * 128 + cn);
            const float m0 = silu_f(acc[i][0] + hn.x);
            const float m1 = silu_f(acc[i][1] + hn.y);
            const float m2 = silu_f(acc[i][2] + hn.z);
            const float m3 = silu_f(acc[i][3] + hn.w);
            asm volatile("red.global.add.v4.f32 [%0], {%1, %2, %3, %4};"
                         :: "l"(g_poolm + b * 128 + cn), "f"(m0), "f"(m1), "f"(m2), "f"(m3)
                         : "memory");
            const float4 hv = *reinterpret_cast<const float4*>(h + (size_t)n * 128 + cn);
            asm volatile("red.global.add.v4.f32 [%0], {%1, %2, %3, %4};"
                         :: "l"(g_pool + b * 128 + cn), "f"(hv.x), "f"(hv.y), "f"(hv.z), "f"(hv.w)
                         : "memory");
        }
    }
    if (t < 32 && n0 + t < N_NODES) atomicAdd(&g_cnt[b_s[t]], 1.0f);
}

// ---------------- k_pool_final (launch #6) ----------------
__global__ void k_pool_final(const float* __restrict__ Wn2,
                             const float* __restrict__ bn2,
                             float* __restrict__ out) {
    __shared__ float pm[128];
    const int g = blockIdx.x;
    const int c = threadIdx.x;
    pm[c] = g_poolm[g * 128 + c];
    __syncthreads();
    float dot = 0.f;
    for (int k = 0; k < 128; k++)
        dot = fmaf(pm[k], __ldg(Wn2 + k * 128 + c), dot);
    const float cnt = g_cnt[g];
    const float s = g_pool[g * 128 + c] + dot + cnt * __ldg(bn2 + c);
    out[g * 128 + c] = s / fmaxf(cnt, 1.0f);
}

// ---------------- launcher ----------------
extern "C" void kernel_launch(void* const* d_in, const int* in_sizes, int n_in,
                              void* d_out, int out_size) {
    const float* h   = (const float*)d_in[0];
    const void*  ei  = d_in[1];
    const float* x   = (const float*)d_in[2];
    const float* ea  = (const float*)d_in[3];
    const void*  bat = d_in[4];
    const float* We1 = (const float*)d_in[5];
    const float* be1 = (const float*)d_in[6];
    const float* We2 = (const float*)d_in[7];
    const float* be2 = (const float*)d_in[8];
    const float* Wn1 = (const float*)d_in[9];
    const float* bn1 = (const float*)d_in[10];
    const float* Wn2 = (const float*)d_in[11];
    const float* bn2 = (const float*)d_in[12];
    float* out = (float*)d_out;

    cudaFuncSetAttribute(k_pre,  cudaFuncAttributeMaxDynamicSharedMemorySize, PRE_SMEM_BYTES);
    cudaFuncSetAttribute(k_edge, cudaFuncAttributeMaxDynamicSharedMemorySize, EDGE_SMEM_BYTES);
    cudaFuncSetAttribute(k_node, cudaFuncAttributeMaxDynamicSharedMemorySize, NODE_SMEM_BYTES);

    k_init<<<(N_NODES * HID / 4 + 255) / 256, 256>>>(ei);                       // #1
    k_cvt_idx<<<(N_EDGES + 255) / 256, 256>>>(ei, bat);                         // #2
    k_pre<<<PGRID, 512, PRE_SMEM_BYTES>>>(h, We1, be1, Wn1, bn1);               // #3
    k_edge<<<EGRID, 512, EDGE_SMEM_BYTES>>>(x, ea, We1, We2, be2);              // #4 (ncu slot)
    k_node<<<(N_NODES + NTILE - 1) / NTILE, 256, NODE_SMEM_BYTES>>>(h, Wn1);    // #5
    k_pool_final<<<N_GRAPHS, HID>>>(Wn2, bn2, out);                             // #6
}

// round 14
// speedup vs baseline: 1.0676x; 1.0676x over previous
#include <cuda_runtime.h>
#include <cuda_bf16.h>
#include <cuda_fp16.h>
#include <cstdint>

#define N_NODES  50000
#define N_EDGES  800000
#define HID      128
#define EDGE_D   16
#define N_GRAPHS 64

#define ETILE 128
#define NTILE 32
#define NUM_ETILES (N_EDGES / ETILE)
#define NUM_PTILES ((N_NODES + 31) / 32)
#define EGRID 304
#define PGRID 152

// ---------------- device scratch (static, no allocation) ----------------
__device__ float g_hAB[(size_t)N_NODES * 256];   // hA | hB  (51.2 MB)
__device__ float g_hn1[(size_t)N_NODES * 128];   // h @ Wn1a + bn1 (25.6 MB)
__device__ float g_agg[(size_t)N_NODES * HID];   // scatter target (25.6 MB)
__device__ float g_pool[N_GRAPHS * HID];         // sum of h per graph
__device__ float g_poolm[N_GRAPHS * HID];        // sum of mid per graph
__device__ float g_cnt[N_GRAPHS];
__device__ int   g_row[N_EDGES];
__device__ int   g_col[N_EDGES];
__device__ int   g_batch[N_NODES];
__device__ int   g_is64;

__device__ __forceinline__ float silu_f(float v) {
    return __fdividef(v, 1.0f + __expf(-v));
}

// bf16 mma m16n8k16 (k_pre)
__device__ __forceinline__ void mma_bf16(float* d, uint32_t a0, uint32_t a1,
                                         uint32_t a2, uint32_t a3,
                                         uint32_t b0, uint32_t b1) {
    asm volatile(
        "mma.sync.aligned.m16n8k16.row.col.f32.bf16.bf16.f32 "
        "{%0,%1,%2,%3}, {%4,%5,%6,%7}, {%8,%9}, {%0,%1,%2,%3};"
        : "+f"(d[0]), "+f"(d[1]), "+f"(d[2]), "+f"(d[3])
        : "r"(a0), "r"(a1), "r"(a2), "r"(a3), "r"(b0), "r"(b1));
}

// fp16 mma m16n8k16 (k_edge)
__device__ __forceinline__ void mma_f16(float* d, uint32_t a0, uint32_t a1,
                                        uint32_t a2, uint32_t a3,
                                        uint32_t b0, uint32_t b1) {
    asm volatile(
        "mma.sync.aligned.m16n8k16.row.col.f32.f16.f16.f32 "
        "{%0,%1,%2,%3}, {%4,%5,%6,%7}, {%8,%9}, {%0,%1,%2,%3};"
        : "+f"(d[0]), "+f"(d[1]), "+f"(d[2]), "+f"(d[3])
        : "r"(a0), "r"(a1), "r"(a2), "r"(a3), "r"(b0), "r"(b1));
}

__device__ __forceinline__ void ldsm4(uint32_t* r, uint32_t addr) {
    asm volatile("ldmatrix.sync.aligned.m8n8.x4.shared.b16 {%0,%1,%2,%3}, [%4];"
                 : "=r"(r[0]), "=r"(r[1]), "=r"(r[2]), "=r"(r[3]) : "r"(addr));
}

__device__ __forceinline__ uint2 pack_hi4(float a, float b, float c, float d,
                                          float& ra, float& rb, float& rc, float& rd) {
    const __nv_bfloat16 ha = __float2bfloat16(a);
    const __nv_bfloat16 hb = __float2bfloat16(b);
    const __nv_bfloat16 hc = __float2bfloat16(c);
    const __nv_bfloat16 hd = __float2bfloat16(d);
    ra = a - __bfloat162float(ha);
    rb = b - __bfloat162float(hb);
    rc = c - __bfloat162float(hc);
    rd = d - __bfloat162float(hd);
    __nv_bfloat162 p0; p0.x = ha; p0.y = hb;
    __nv_bfloat162 p1; p1.x = hc; p1.y = hd;
    uint2 r;
    r.x = *reinterpret_cast<uint32_t*>(&p0);
    r.y = *reinterpret_cast<uint32_t*>(&p1);
    return r;
}
__device__ __forceinline__ uint2 pack_bf4(float a, float b, float c, float d) {
    __nv_bfloat162 p0; p0.x = __float2bfloat16(a); p0.y = __float2bfloat16(b);
    __nv_bfloat162 p1; p1.x = __float2bfloat16(c); p1.y = __float2bfloat16(d);
    uint2 r;
    r.x = *reinterpret_cast<uint32_t*>(&p0);
    r.y = *reinterpret_cast<uint32_t*>(&p1);
    return r;
}

// ---------------- init (launch #1) ----------------
__global__ void k_init(const void* __restrict__ ei) {
    const int i = blockIdx.x * blockDim.x + threadIdx.x;
    if (i < (N_NODES * HID) / 4)
        reinterpret_cast<float4*>(g_agg)[i] = make_float4(0.f, 0.f, 0.f, 0.f);
    if (i < N_GRAPHS * HID) { g_pool[i] = 0.f; g_poolm[i] = 0.f; }
    if (i < N_GRAPHS)       g_cnt[i] = 0.f;
    if (i == 0) {
        const unsigned int* p = (const unsigned int*)ei;
        int is64 = 1;
        for (int j = 0; j < 16; j++) if (p[2 * j + 1] != 0u) is64 = 0;
        g_is64 = is64;
    }
}

// ---------------- index conversion (launch #2) ----------------
__global__ void k_cvt_idx(const void* __restrict__ ei, const void* __restrict__ batch) {
    const int i = blockIdx.x * blockDim.x + threadIdx.x;
    const bool is64 = (g_is64 != 0);
    if (i < N_EDGES) {
        if (is64) {
            const long long* p = (const long long*)ei;
            g_row[i] = (int)p[i];
            g_col[i] = (int)p[N_EDGES + i];
        } else {
            const int* p = (const int*)ei;
            g_row[i] = p[i];
            g_col[i] = p[N_EDGES + i];
        }
    }
    if (i < N_NODES) {
        if (is64) g_batch[i] = (int)((const long long*)batch)[i];
        else      g_batch[i] = ((const int*)batch)[i];
    }
}

// ---------------- k_pre (launch #3): persistent bf16 3-term pre-GEMM ----------------
#define BSTRIDE 136   // b16 elements per row (272 B) -> conflict-free fragments

#define PB_BH   0                  // 384x136 bf16 hi = 104448 B
#define PB_BL   104448             // 104448 B
#define PB_AH   208896             // 32x136 bf16 hi = 8704 B
#define PB_AL   217600             // 8704 B
#define PB_BIAS 226304             // 384 f32 = 1536 B
#define PRE_SMEM_BYTES 227840

__global__ __launch_bounds__(512, 1) void k_pre(const float* __restrict__ h,
                                                const float* __restrict__ We1,
                                                const float* __restrict__ be1,
                                                const float* __restrict__ Wn1,
                                                const float* __restrict__ bn1) {
    extern __shared__ char smem[];
    __nv_bfloat16* Bh = reinterpret_cast<__nv_bfloat16*>(smem + PB_BH);
    __nv_bfloat16* Bl = reinterpret_cast<__nv_bfloat16*>(smem + PB_BL);
    __nv_bfloat16* Ah = reinterpret_cast<__nv_bfloat16*>(smem + PB_AH);
    __nv_bfloat16* Al = reinterpret_cast<__nv_bfloat16*>(smem + PB_AL);
    float* bias_s = reinterpret_cast<float*>(smem + PB_BIAS);

    const int t = threadIdx.x;
    const int w = t >> 5, lane = t & 31;

    for (int i = t; i < 384 * 128; i += 512) {
        const int c = i >> 7, k = i & 127;
        float v;
        if (c < 128)       v = We1[k * 128 + c];
        else if (c < 256)  v = We1[(128 + k) * 128 + (c - 128)];
        else               v = Wn1[k * 128 + (c - 256)];
        const __nv_bfloat16 hi = __float2bfloat16(v);
        Bh[c * BSTRIDE + k] = hi;
        Bl[c * BSTRIDE + k] = __float2bfloat16(v - __bfloat162float(hi));
    }
    for (int i = t; i < 384; i += 512) {
        float b = 0.f;
        if (i < 128)      b = be1[i];
        else if (i >= 256) b = bn1[i - 256];
        bias_s[i] = b;
    }
    __syncthreads();

    const int mt = w & 1;
    const int nb = w >> 1;
    const int g  = lane >> 2;
    const int tq = lane & 3;

    for (int tile = blockIdx.x; tile < NUM_PTILES; tile += PGRID) {
        const int n0 = tile * 32;
        __syncthreads();
        for (int idx = t; idx < 1024; idx += 512) {
            const int n = idx >> 5, kq = idx & 31;
            float4 v = make_float4(0.f, 0.f, 0.f, 0.f);
            if (n0 + n < N_NODES)
                v = *reinterpret_cast<const float4*>(h + (size_t)(n0 + n) * 128 + kq * 4);
            float la, lb, lc, ld;
            const uint2 hv = pack_hi4(v.x, v.y, v.z, v.w, la, lb, lc, ld);
            *reinterpret_cast<uint2*>(Ah + n * BSTRIDE + kq * 4) = hv;
            *reinterpret_cast<uint2*>(Al + n * BSTRIDE + kq * 4) = pack_bf4(la, lb, lc, ld);
        }
        __syncthreads();

        float d[6][4];
#pragma unroll
        for (int nt = 0; nt < 6; nt++)
#pragma unroll
            for (int j = 0; j < 4; j++) d[nt][j] = 0.f;

        const int arow = mt * 16 + g;
#pragma unroll
        for (int ks = 0; ks < 8; ks++) {
            const int kb = ks * 16;
            const __nv_bfloat16* Ap = Ah + arow * BSTRIDE + 2 * tq + kb;
            const uint32_t a0 = *reinterpret_cast<const uint32_t*>(Ap);
            const uint32_t a1 = *reinterpret_cast<const uint32_t*>(Ap + 8 * BSTRIDE);
            const uint32_t a2 = *reinterpret_cast<const uint32_t*>(Ap + 8);
            const uint32_t a3 = *reinterpret_cast<const uint32_t*>(Ap + 8 * BSTRIDE + 8);
            const __nv_bfloat16* Lp = Al + arow * BSTRIDE + 2 * tq + kb;
            const uint32_t l0 = *reinterpret_cast<const uint32_t*>(Lp);
            const uint32_t l1 = *reinterpret_cast<const uint32_t*>(Lp + 8 * BSTRIDE);
            const uint32_t l2 = *reinterpret_cast<const uint32_t*>(Lp + 8);
            const uint32_t l3 = *reinterpret_cast<const uint32_t*>(Lp + 8 * BSTRIDE + 8);
            uint32_t bf[6][2];
#pragma unroll
            for (int nt = 0; nt < 6; nt++) {
                const __nv_bfloat16* Bp = Bh + (nb * 48 + nt * 8 + g) * BSTRIDE + 2 * tq + kb;
                bf[nt][0] = *reinterpret_cast<const uint32_t*>(Bp);
                bf[nt][1] = *reinterpret_cast<const uint32_t*>(Bp + 8);
            }
#pragma unroll
            for (int nt = 0; nt < 6; nt++) {
                mma_bf16(d[nt], a0, a1, a2, a3, bf[nt][0], bf[nt][1]);
                mma_bf16(d[nt], l0, l1, l2, l3, bf[nt][0], bf[nt][1]);
            }
#pragma unroll
            for (int nt = 0; nt < 6; nt++) {
                const __nv_bfloat16* Bp = Bl + (nb * 48 + nt * 8 + g) * BSTRIDE + 2 * tq + kb;
                bf[nt][0] = *reinterpret_cast<const uint32_t*>(Bp);
                bf[nt][1] = *reinterpret_cast<const uint32_t*>(Bp + 8);
            }
#pragma unroll
            for (int nt = 0; nt < 6; nt++)
                mma_bf16(d[nt], a0, a1, a2, a3, bf[nt][0], bf[nt][1]);
        }

        const int r0 = n0 + mt * 16 + g;
        const int r1 = r0 + 8;
#pragma unroll
        for (int nt = 0; nt < 6; nt++) {
            const int col = nb * 48 + nt * 8 + 2 * tq;
            const float b0 = bias_s[col], b1 = bias_s[col + 1];
            float2 v0 = make_float2(d[nt][0] + b0, d[nt][1] + b1);
            float2 v1 = make_float2(d[nt][2] + b0, d[nt][3] + b1);
            if (col < 256) {
                if (r0 < N_NODES) *reinterpret_cast<float2*>(g_hAB + (size_t)r0 * 256 + col) = v0;
                if (r1 < N_NODES) *reinterpret_cast<float2*>(g_hAB + (size_t)r1 * 256 + col) = v1;
            } else {
                if (r0 < N_NODES) *reinterpret_cast<float2*>(g_hn1 + (size_t)r0 * 128 + col - 256) = v0;
                if (r1 < N_NODES) *reinterpret_cast<float2*>(g_hn1 + (size_t)r1 * 128 + col - 256) = v1;
            }
        }
    }
}

// ---------------- fused edge kernel (launch #4; 2 CTAs/SM, ETILE=128, fp16 1-term) ----
#define SB_W2H   0                 // 128x136 fp16 = 34816 B (W2^T)
#define SB_UH    34816             // 34816 B  u (fp16)
#define SB_W1E   69632             // 2048 f32 = 8192 B
#define SB_W1R   77824             // 512 B
#define SB_BE2   78336             // 512 B
#define EDGE_SMEM_BYTES 78848

__global__ __launch_bounds__(512, 2) void k_edge(const float* __restrict__ x,
                                                 const float* __restrict__ ea,
                                                 const float* __restrict__ We1,
                                                 const float* __restrict__ We2,
                                                 const float* __restrict__ be2) {
    extern __shared__ char smem[];
    __half* w2h = reinterpret_cast<__half*>(smem + SB_W2H);
    __half* uhi = reinterpret_cast<__half*>(smem + SB_UH);
    float* W1e_s = reinterpret_cast<float*>(smem + SB_W1E);
    float* W1r_s = reinterpret_cast<float*>(smem + SB_W1R);
    float* be2_s = reinterpret_cast<float*>(smem + SB_BE2);

    const int t = threadIdx.x;
    const int w = t >> 5, lane = t & 31;

    // stage W2^T fp16 (once per block): We2 is [k][c] -> w2h[c][k]
    for (int i = t; i < 16384; i += 512) {
        const int k = i >> 7, c = i & 127;
        w2h[c * BSTRIDE + k] = __float2half_rn(We2[i]);
    }
    for (int i = t; i < 2048; i += 512) W1e_s[i] = We1[257 * 128 + i];
    if (t < 128) {
        W1r_s[t] = We1[256 * 128 + t];
        be2_s[t] = be2[t];
    }
    __syncthreads();

    const float4 wr = *reinterpret_cast<const float4*>(W1r_s + lane * 4);

    // Phase-B tiling: 16 warps -> m16 (mt = w&7) x n64 (nh = w>>3)
    const int mt = w & 7;
    const int nh = w >> 3;
    const int g  = lane >> 2;
    const int tq = lane & 3;

    // ldmatrix lane maps
    const int rA = lane & 15;
    const int kA = (lane & 16) ? 8 : 0;
    const int rB = ((lane >> 4) & 1) * 8 + (lane & 7);
    const int kB = (lane & 8) ? 8 : 0;
    const uint32_t uhi_s = (uint32_t)__cvta_generic_to_shared(uhi);
    const uint32_t w2h_s = (uint32_t)__cvta_generic_to_shared(w2h);
    const uint32_t aoff  = (uint32_t)(((mt * 16 + rA) * BSTRIDE + kA) * 2);
    uint32_t boff[2][2];
#pragma unroll
    for (int hf = 0; hf < 2; hf++)
#pragma unroll
        for (int p = 0; p < 2; p++)
            boff[hf][p] = (uint32_t)(((nh * 64 + hf * 32 + p * 16 + rB) * BSTRIDE + kB) * 2);

    for (int tile = blockIdx.x; tile < NUM_ETILES; tile += EGRID) {
        const int e0 = tile * ETILE;
        __syncthreads();   // protect u buffer vs previous tile readers

        // ---- Phase A: 16 warps x 8 edges; u (fp16) -> smem
        {
            const int ebase = w * 8;
            const int co    = lane * 4;
            int r8 = 0, c8 = 0;
            float rad8 = 0.f;
            if (lane < 8) {
                const int eg = e0 + ebase + lane;
                r8 = g_row[eg];
                c8 = g_col[eg];
                const float dx = x[r8 * 3 + 0] - x[c8 * 3 + 0];
                const float dy = x[r8 * 3 + 1] - x[c8 * 3 + 1];
                const float dz = x[r8 * 3 + 2] - x[c8 * 3 + 2];
                rad8 = dx * dx + dy * dy + dz * dz;
            }
            float acc[8][4];
#pragma unroll
            for (int ii = 0; ii < 8; ii++) {
                const int r   = __shfl_sync(0xffffffffu, r8, ii);
                const int c   = __shfl_sync(0xffffffffu, c8, ii);
                const float rad = __shfl_sync(0xffffffffu, rad8, ii);
                const float4 a4 = *reinterpret_cast<const float4*>(g_hAB + (size_t)r * 256 + co);
                const float4 b4 = *reinterpret_cast<const float4*>(g_hAB + (size_t)c * 256 + 128 + co);
                acc[ii][0] = fmaf(rad, wr.x, a4.x + b4.x);
                acc[ii][1] = fmaf(rad, wr.y, a4.y + b4.y);
                acc[ii][2] = fmaf(rad, wr.z, a4.z + b4.z);
                acc[ii][3] = fmaf(rad, wr.w, a4.w + b4.w);
            }
#pragma unroll
            for (int jb = 0; jb < 4; jb++) {
                float4 wv[4];
#pragma unroll
                for (int q = 0; q < 4; q++)
                    wv[q] = *reinterpret_cast<const float4*>(W1e_s + (jb * 4 + q) * 128 + co);
#pragma unroll
                for (int ii = 0; ii < 8; ii++) {
                    const float4 e4 = __ldg(reinterpret_cast<const float4*>(
                        ea + (size_t)(e0 + ebase + ii) * 16 + jb * 4));
                    const float ev[4] = {e4.x, e4.y, e4.z, e4.w};
#pragma unroll
                    for (int q = 0; q < 4; q++) {
                        acc[ii][0] = fmaf(ev[q], wv[q].x, acc[ii][0]);
                        acc[ii][1] = fmaf(ev[q], wv[q].y, acc[ii][1]);
                        acc[ii][2] = fmaf(ev[q], wv[q].z, acc[ii][2]);
                        acc[ii][3] = fmaf(ev[q], wv[q].w, acc[ii][3]);
                    }
                }
            }
#pragma unroll
            for (int ii = 0; ii < 8; ii++) {
                const int e = ebase + ii;
                __half2 hp0 = __floats2half2_rn(silu_f(acc[ii][0]), silu_f(acc[ii][1]));
                __half2 hp1 = __floats2half2_rn(silu_f(acc[ii][2]), silu_f(acc[ii][3]));
                uint2 hv;
                hv.x = *reinterpret_cast<uint32_t*>(&hp0);
                hv.y = *reinterpret_cast<uint32_t*>(&hp1);
                *reinterpret_cast<uint2*>(uhi + e * BSTRIDE + co) = hv;
            }
        }
        __syncthreads();

        // ---- Phase B: D = u_hi @ W_hi (fp16, LDSM + mma, single term)
        {
            float d[8][4];
#pragma unroll
            for (int nt = 0; nt < 8; nt++)
#pragma unroll
                for (int j = 0; j < 4; j++) d[nt][j] = 0.f;

#pragma unroll
            for (int ks = 0; ks < 8; ks++) {
                const uint32_t kb2 = ks * 32;
                uint32_t ah[4];
                ldsm4(ah, uhi_s + aoff + kb2);
#pragma unroll
                for (int hf = 0; hf < 2; hf++) {
                    uint32_t bf[2][4];
                    ldsm4(bf[0], w2h_s + boff[hf][0] + kb2);
                    ldsm4(bf[1], w2h_s + boff[hf][1] + kb2);
#pragma unroll
                    for (int p = 0; p < 2; p++)
#pragma unroll
                        for (int sub = 0; sub < 2; sub++) {
                            const int nt = hf * 4 + p * 2 + sub;
                            mma_f16(d[nt], ah[0], ah[1], ah[2], ah[3],
                                    bf[p][sub * 2], bf[p][sub * 2 + 1]);
                        }
                }
            }

            // epilogue: silu(+bias), shfl-pair, red.v4 scatter
            const int er0 = g_row[e0 + mt * 16 + g];
            const int er1 = g_row[e0 + mt * 16 + g + 8];
            const bool evenq = (tq & 1) == 0;
#pragma unroll
            for (int nt = 0; nt < 8; nt++) {
                const int col = nh * 64 + nt * 8 + 2 * tq;
                const float b0v = be2_s[col];
                const float b1v = be2_s[col + 1];
                const float v00 = silu_f(d[nt][0] + b0v);
                const float v01 = silu_f(d[nt][1] + b1v);
                const float v10 = silu_f(d[nt][2] + b0v);
                const float v11 = silu_f(d[nt][3] + b1v);
                const float p00 = __shfl_xor_sync(0xffffffffu, v00, 1);
                const float p01 = __shfl_xor_sync(0xffffffffu, v01, 1);
                const float p10 = __shfl_xor_sync(0xffffffffu, v10, 1);
                const float p11 = __shfl_xor_sync(0xffffffffu, v11, 1);
                const int colbase = nh * 64 + nt * 8 + (tq & 2) * 2;
                if (evenq) {
                    asm volatile("red.global.add.v4.f32 [%0], {%1, %2, %3, %4};"
                                 :: "l"(g_agg + (size_t)er0 * 128 + colbase),
                                    "f"(v00), "f"(v01), "f"(p00), "f"(p01) : "memory");
                } else {
                    asm volatile("red.global.add.v4.f32 [%0], {%1, %2, %3, %4};"
                                 :: "l"(g_agg + (size_t)er1 * 128 + colbase),
                                    "f"(p10), "f"(p11), "f"(v10), "f"(v11) : "memory");
                }
            }
        }
    }
}

// ---------------- k_node (launch #5): mid = silu(hn1 + agg@Wn1b); scatter to pools ----
#define NODE_SMEM_FLOATS (128 * 36 + 32)
#define NODE_SMEM_BYTES  (NODE_SMEM_FLOATS * 4)

__global__ __launch_bounds__(256) void k_node(const float* __restrict__ h,
                                              const float* __restrict__ Wn1) {
    extern __shared__ float sm[];
    float* a_s = sm;
    int*   b_s = reinterpret_cast<int*>(sm + 128 * 36);

    const int n0 = blockIdx.x * NTILE;
    const int t = threadIdx.x;
    {
        const int n  = t >> 3;
        const int k4 = t & 7;
        const int ng = n0 + n;
#pragma unroll
        for (int j = 0; j < 4; j++) {
            const int k = k4 * 16 + j * 4;
            float4 w = make_float4(0.f, 0.f, 0.f, 0.f);
            if (ng < N_NODES)
                w = *reinterpret_cast<const float4*>(g_agg + (size_t)ng * 128 + k);
            a_s[(k + 0) * 36 + n] = w.x;
            a_s[(k + 1) * 36 + n] = w.y;
            a_s[(k + 2) * 36 + n] = w.z;
            a_s[(k + 3) * 36 + n] = w.w;
        }
        if (t < 32) b_s[t] = (n0 + t < N_NODES) ? g_batch[n0 + t] : 0;
    }
    __syncthreads();

    const int cg = t & 31;
    const int ng = t >> 5;
    const int cn = cg * 4;
    float acc[4][4];
#pragma unroll
    for (int i = 0; i < 4; i++)
#pragma unroll
        for (int j = 0; j < 4; j++) acc[i][j] = 0.f;

    for (int k = 0; k < 128; k++) {
        float av[4];
#pragma unroll
        for (int i = 0; i < 4; i++) av[i] = a_s[k * 36 + ng * 4 + i];
        const float4 w = __ldg(reinterpret_cast<const float4*>(Wn1 + (128 + k) * 128 + cn));
        const float wv[4] = {w.x, w.y, w.z, w.w};
#pragma unroll
        for (int i = 0; i < 4; i++)
#pragma unroll
            for (int j = 0; j < 4; j++) acc[i][j] = fmaf(av[i], wv[j], acc[i][j]);
    }
#pragma unroll
    for (int i = 0; i < 4; i++) {
        const int n = n0 + ng * 4 + i;
        if (n < N_NODES) {
            const int b = b_s[ng * 4 + i];
            const float4 hn = *reinterpret_cast<const float4*>(g_hn1 + (size_t)n * 128 + cn);
            const float m0 = silu_f(acc[i][0] + hn.x);
            const float m1 = silu_f(acc[i][1] + hn.y);
            const float m2 = silu_f(acc[i][2] + hn.z);
            const float m3 = silu_f(acc[i][3] + hn.w);
            asm volatile("red.global.add.v4.f32 [%0], {%1, %2, %3, %4};"
                         :: "l"(g_poolm + b * 128 + cn), "f"(m0), "f"(m1), "f"(m2), "f"(m3)
                         : "memory");
            const float4 hv = *reinterpret_cast<const float4*>(h + (size_t)n * 128 + cn);
            asm volatile("red.global.add.v4.f32 [%0], {%1, %2, %3, %4};"
                         :: "l"(g_pool + b * 128 + cn), "f"(hv.x), "f"(hv.y), "f"(hv.z), "f"(hv.w)
                         : "memory");
        }
    }
    if (t < 32 && n0 + t < N_NODES) atomicAdd(&g_cnt[b_s[t]], 1.0f);
}

// ---------------- k_pool_final (launch #6) ----------------
__global__ void k_pool_final(const float* __restrict__ Wn2,
                             const float* __restrict__ bn2,
                             float* __restrict__ out) {
    __shared__ float pm[128];
    const int g = blockIdx.x;
    const int c = threadIdx.x;
    pm[c] = g_poolm[g * 128 + c];
    __syncthreads();
    float dot = 0.f;
    for (int k = 0; k < 128; k++)
        dot = fmaf(pm[k], __ldg(Wn2 + k * 128 + c), dot);
    const float cnt = g_cnt[g];
    const float s = g_pool[g * 128 + c] + dot + cnt * __ldg(bn2 + c);
    out[g * 128 + c] = s / fmaxf(cnt, 1.0f);
}

// ---------------- launcher ----------------
extern "C" void kernel_launch(void* const* d_in, const int* in_sizes, int n_in,
                              void* d_out, int out_size) {
    const float* h   = (const float*)d_in[0];
    const void*  ei  = d_in[1];
    const float* x   = (const float*)d_in[2];
    const float* ea  = (const float*)d_in[3];
    const void*  bat = d_in[4];
    const float* We1 = (const float*)d_in[5];
    const float* be1 = (const float*)d_in[6];
    const float* We2 = (const float*)d_in[7];
    const float* be2 = (const float*)d_in[8];
    const float* Wn1 = (const float*)d_in[9];
    const float* bn1 = (const float*)d_in[10];
    const float* Wn2 = (const float*)d_in[11];
    const float* bn2 = (const float*)d_in[12];
    float* out = (float*)d_out;

    cudaFuncSetAttribute(k_pre,  cudaFuncAttributeMaxDynamicSharedMemorySize, PRE_SMEM_BYTES);
    cudaFuncSetAttribute(k_edge, cudaFuncAttributeMaxDynamicSharedMemorySize, EDGE_SMEM_BYTES);
    cudaFuncSetAttribute(k_node, cudaFuncAttributeMaxDynamicSharedMemorySize, NODE_SMEM_BYTES);

    k_init<<<(N_NODES * HID / 4 + 255) / 256, 256>>>(ei);                       // #1
    k_cvt_idx<<<(N_EDGES + 255) / 256, 256>>>(ei, bat);                         // #2
    k_pre<<<PGRID, 512, PRE_SMEM_BYTES>>>(h, We1, be1, Wn1, bn1);               // #3
    k_edge<<<EGRID, 512, EDGE_SMEM_BYTES>>>(x, ea, We1, We2, be2);              // #4 (ncu slot)
    k_node<<<(N_NODES + NTILE - 1) / NTILE, 256, NODE_SMEM_BYTES>>>(h, Wn1);    // #5
    k_pool_final<<<N_GRAPHS, HID>>>(Wn2, bn2, out);                             // #6
}

// round 15
// speedup vs baseline: 1.1707x; 1.0965x over previous
#include <cuda_runtime.h>
#include <cuda_bf16.h>
#include <cuda_fp16.h>
#include <cstdint>

#define N_NODES  50000
#define N_EDGES  800000
#define HID      128
#define EDGE_D   16
#define N_GRAPHS 64

#define ETILE 128
#define NTILE 32
#define NUM_ETILES (N_EDGES / ETILE)
#define NUM_PTILES ((N_NODES + 31) / 32)
#define EGRID 304
#define PGRID 152

// ---------------- device scratch (static, no allocation) ----------------
__device__ __half g_hAB[(size_t)N_NODES * 256];  // hA | hB  fp16 (25.6 MB)
__device__ float g_hn1[(size_t)N_NODES * 128];   // h @ Wn1a + bn1 (25.6 MB)
__device__ float g_agg[(size_t)N_NODES * HID];   // scatter target (25.6 MB)
__device__ float g_pool[N_GRAPHS * HID];         // sum of h per graph
__device__ float g_poolm[N_GRAPHS * HID];        // sum of mid per graph
__device__ float g_cnt[N_GRAPHS];
__device__ int   g_row[N_EDGES];
__device__ int   g_col[N_EDGES];
__device__ int   g_batch[N_NODES];
__device__ int   g_is64;

__device__ __forceinline__ float silu_f(float v) {
    return __fdividef(v, 1.0f + __expf(-v));
}

// bf16 mma m16n8k16 (k_pre)
__device__ __forceinline__ void mma_bf16(float* d, uint32_t a0, uint32_t a1,
                                         uint32_t a2, uint32_t a3,
                                         uint32_t b0, uint32_t b1) {
    asm volatile(
        "mma.sync.aligned.m16n8k16.row.col.f32.bf16.bf16.f32 "
        "{%0,%1,%2,%3}, {%4,%5,%6,%7}, {%8,%9}, {%0,%1,%2,%3};"
        : "+f"(d[0]), "+f"(d[1]), "+f"(d[2]), "+f"(d[3])
        : "r"(a0), "r"(a1), "r"(a2), "r"(a3), "r"(b0), "r"(b1));
}

// fp16 mma m16n8k16 (k_edge)
__device__ __forceinline__ void mma_f16(float* d, uint32_t a0, uint32_t a1,
                                        uint32_t a2, uint32_t a3,
                                        uint32_t b0, uint32_t b1) {
    asm volatile(
        "mma.sync.aligned.m16n8k16.row.col.f32.f16.f16.f32 "
        "{%0,%1,%2,%3}, {%4,%5,%6,%7}, {%8,%9}, {%0,%1,%2,%3};"
        : "+f"(d[0]), "+f"(d[1]), "+f"(d[2]), "+f"(d[3])
        : "r"(a0), "r"(a1), "r"(a2), "r"(a3), "r"(b0), "r"(b1));
}

__device__ __forceinline__ void ldsm4(uint32_t* r, uint32_t addr) {
    asm volatile("ldmatrix.sync.aligned.m8n8.x4.shared.b16 {%0,%1,%2,%3}, [%4];"
                 : "=r"(r[0]), "=r"(r[1]), "=r"(r[2]), "=r"(r[3]) : "r"(addr));
}

__device__ __forceinline__ uint2 pack_hi4(float a, float b, float c, float d,
                                          float& ra, float& rb, float& rc, float& rd) {
    const __nv_bfloat16 ha = __float2bfloat16(a);
    const __nv_bfloat16 hb = __float2bfloat16(b);
    const __nv_bfloat16 hc = __float2bfloat16(c);
    const __nv_bfloat16 hd = __float2bfloat16(d);
    ra = a - __bfloat162float(ha);
    rb = b - __bfloat162float(hb);
    rc = c - __bfloat162float(hc);
    rd = d - __bfloat162float(hd);
    __nv_bfloat162 p0; p0.x = ha; p0.y = hb;
    __nv_bfloat162 p1; p1.x = hc; p1.y = hd;
    uint2 r;
    r.x = *reinterpret_cast<uint32_t*>(&p0);
    r.y = *reinterpret_cast<uint32_t*>(&p1);
    return r;
}
__device__ __forceinline__ uint2 pack_bf4(float a, float b, float c, float d) {
    __nv_bfloat162 p0; p0.x = __float2bfloat16(a); p0.y = __float2bfloat16(b);
    __nv_bfloat162 p1; p1.x = __float2bfloat16(c); p1.y = __float2bfloat16(d);
    uint2 r;
    r.x = *reinterpret_cast<uint32_t*>(&p0);
    r.y = *reinterpret_cast<uint32_t*>(&p1);
    return r;
}

// ---------------- init (launch #1) ----------------
__global__ void k_init(const void* __restrict__ ei) {
    const int i = blockIdx.x * blockDim.x + threadIdx.x;
    if (i < (N_NODES * HID) / 4)
        reinterpret_cast<float4*>(g_agg)[i] = make_float4(0.f, 0.f, 0.f, 0.f);
    if (i < N_GRAPHS * HID) { g_pool[i] = 0.f; g_poolm[i] = 0.f; }
    if (i < N_GRAPHS)       g_cnt[i] = 0.f;
    if (i == 0) {
        const unsigned int* p = (const unsigned int*)ei;
        int is64 = 1;
        for (int j = 0; j < 16; j++) if (p[2 * j + 1] != 0u) is64 = 0;
        g_is64 = is64;
    }
}

// ---------------- index conversion (launch #2) ----------------
__global__ void k_cvt_idx(const void* __restrict__ ei, const void* __restrict__ batch) {
    const int i = blockIdx.x * blockDim.x + threadIdx.x;
    const bool is64 = (g_is64 != 0);
    if (i < N_EDGES) {
        if (is64) {
            const long long* p = (const long long*)ei;
            g_row[i] = (int)p[i];
            g_col[i] = (int)p[N_EDGES + i];
        } else {
            const int* p = (const int*)ei;
            g_row[i] = p[i];
            g_col[i] = p[N_EDGES + i];
        }
    }
    if (i < N_NODES) {
        if (is64) g_batch[i] = (int)((const long long*)batch)[i];
        else      g_batch[i] = ((const int*)batch)[i];
    }
}

// ---------------- k_pre (launch #3): persistent bf16 3-term pre-GEMM ----------------
#define BSTRIDE 136   // b16 elements per row (272 B) -> conflict-free fragments

#define PB_BH   0                  // 384x136 bf16 hi = 104448 B
#define PB_BL   104448             // 104448 B
#define PB_AH   208896             // 32x136 bf16 hi = 8704 B
#define PB_AL   217600             // 8704 B
#define PB_BIAS 226304             // 384 f32 = 1536 B
#define PRE_SMEM_BYTES 227840

__global__ __launch_bounds__(512, 1) void k_pre(const float* __restrict__ h,
                                                const float* __restrict__ We1,
                                                const float* __restrict__ be1,
                                                const float* __restrict__ Wn1,
                                                const float* __restrict__ bn1) {
    extern __shared__ char smem[];
    __nv_bfloat16* Bh = reinterpret_cast<__nv_bfloat16*>(smem + PB_BH);
    __nv_bfloat16* Bl = reinterpret_cast<__nv_bfloat16*>(smem + PB_BL);
    __nv_bfloat16* Ah = reinterpret_cast<__nv_bfloat16*>(smem + PB_AH);
    __nv_bfloat16* Al = reinterpret_cast<__nv_bfloat16*>(smem + PB_AL);
    float* bias_s = reinterpret_cast<float*>(smem + PB_BIAS);

    const int t = threadIdx.x;
    const int w = t >> 5, lane = t & 31;

    for (int i = t; i < 384 * 128; i += 512) {
        const int c = i >> 7, k = i & 127;
        float v;
        if (c < 128)       v = We1[k * 128 + c];
        else if (c < 256)  v = We1[(128 + k) * 128 + (c - 128)];
        else               v = Wn1[k * 128 + (c - 256)];
        const __nv_bfloat16 hi = __float2bfloat16(v);
        Bh[c * BSTRIDE + k] = hi;
        Bl[c * BSTRIDE + k] = __float2bfloat16(v - __bfloat162float(hi));
    }
    for (int i = t; i < 384; i += 512) {
        float b = 0.f;
        if (i < 128)      b = be1[i];
        else if (i >= 256) b = bn1[i - 256];
        bias_s[i] = b;
    }
    __syncthreads();

    const int mt = w & 1;
    const int nb = w >> 1;
    const int g  = lane >> 2;
    const int tq = lane & 3;

    for (int tile = blockIdx.x; tile < NUM_PTILES; tile += PGRID) {
        const int n0 = tile * 32;
        __syncthreads();
        for (int idx = t; idx < 1024; idx += 512) {
            const int n = idx >> 5, kq = idx & 31;
            float4 v = make_float4(0.f, 0.f, 0.f, 0.f);
            if (n0 + n < N_NODES)
                v = *reinterpret_cast<const float4*>(h + (size_t)(n0 + n) * 128 + kq * 4);
            float la, lb, lc, ld;
            const uint2 hv = pack_hi4(v.x, v.y, v.z, v.w, la, lb, lc, ld);
            *reinterpret_cast<uint2*>(Ah + n * BSTRIDE + kq * 4) = hv;
            *reinterpret_cast<uint2*>(Al + n * BSTRIDE + kq * 4) = pack_bf4(la, lb, lc, ld);
        }
        __syncthreads();

        float d[6][4];
#pragma unroll
        for (int nt = 0; nt < 6; nt++)
#pragma unroll
            for (int j = 0; j < 4; j++) d[nt][j] = 0.f;

        const int arow = mt * 16 + g;
#pragma unroll
        for (int ks = 0; ks < 8; ks++) {
            const int kb = ks * 16;
            const __nv_bfloat16* Ap = Ah + arow * BSTRIDE + 2 * tq + kb;
            const uint32_t a0 = *reinterpret_cast<const uint32_t*>(Ap);
            const uint32_t a1 = *reinterpret_cast<const uint32_t*>(Ap + 8 * BSTRIDE);
            const uint32_t a2 = *reinterpret_cast<const uint32_t*>(Ap + 8);
            const uint32_t a3 = *reinterpret_cast<const uint32_t*>(Ap + 8 * BSTRIDE + 8);
            const __nv_bfloat16* Lp = Al + arow * BSTRIDE + 2 * tq + kb;
            const uint32_t l0 = *reinterpret_cast<const uint32_t*>(Lp);
            const uint32_t l1 = *reinterpret_cast<const uint32_t*>(Lp + 8 * BSTRIDE);
            const uint32_t l2 = *reinterpret_cast<const uint32_t*>(Lp + 8);
            const uint32_t l3 = *reinterpret_cast<const uint32_t*>(Lp + 8 * BSTRIDE + 8);
            uint32_t bf[6][2];
#pragma unroll
            for (int nt = 0; nt < 6; nt++) {
                const __nv_bfloat16* Bp = Bh + (nb * 48 + nt * 8 + g) * BSTRIDE + 2 * tq + kb;
                bf[nt][0] = *reinterpret_cast<const uint32_t*>(Bp);
                bf[nt][1] = *reinterpret_cast<const uint32_t*>(Bp + 8);
            }
#pragma unroll
            for (int nt = 0; nt < 6; nt++) {
                mma_bf16(d[nt], a0, a1, a2, a3, bf[nt][0], bf[nt][1]);
                mma_bf16(d[nt], l0, l1, l2, l3, bf[nt][0], bf[nt][1]);
            }
#pragma unroll
            for (int nt = 0; nt < 6; nt++) {
                const __nv_bfloat16* Bp = Bl + (nb * 48 + nt * 8 + g) * BSTRIDE + 2 * tq + kb;
                bf[nt][0] = *reinterpret_cast<const uint32_t*>(Bp);
                bf[nt][1] = *reinterpret_cast<const uint32_t*>(Bp + 8);
            }
#pragma unroll
            for (int nt = 0; nt < 6; nt++)
                mma_bf16(d[nt], a0, a1, a2, a3, bf[nt][0], bf[nt][1]);
        }

        const int r0 = n0 + mt * 16 + g;
        const int r1 = r0 + 8;
#pragma unroll
        for (int nt = 0; nt < 6; nt++) {
            const int col = nb * 48 + nt * 8 + 2 * tq;
            const float b0 = bias_s[col], b1 = bias_s[col + 1];
            const float v00 = d[nt][0] + b0, v01 = d[nt][1] + b1;
            const float v10 = d[nt][2] + b0, v11 = d[nt][3] + b1;
            if (col < 256) {
                // fp16 store into gather table
                const __half2 h0 = __floats2half2_rn(v00, v01);
                const __half2 h1 = __floats2half2_rn(v10, v11);
                if (r0 < N_NODES) *reinterpret_cast<__half2*>(g_hAB + (size_t)r0 * 256 + col) = h0;
                if (r1 < N_NODES) *reinterpret_cast<__half2*>(g_hAB + (size_t)r1 * 256 + col) = h1;
            } else {
                if (r0 < N_NODES)
                    *reinterpret_cast<float2*>(g_hn1 + (size_t)r0 * 128 + col - 256) = make_float2(v00, v01);
                if (r1 < N_NODES)
                    *reinterpret_cast<float2*>(g_hn1 + (size_t)r1 * 128 + col - 256) = make_float2(v10, v11);
            }
        }
    }
}

// ---------------- fused edge kernel (launch #4; 2 CTAs/SM, ETILE=128, fp16 1-term) ----
#define SB_W2H   0                 // 128x136 fp16 = 34816 B (W2^T)
#define SB_UH    34816             // 34816 B  u (fp16)
#define SB_W1E   69632             // 2048 f32 = 8192 B
#define SB_W1R   77824             // 512 B
#define SB_BE2   78336             // 512 B
#define EDGE_SMEM_BYTES 78848

__global__ __launch_bounds__(512, 2) void k_edge(const float* __restrict__ x,
                                                 const float* __restrict__ ea,
                                                 const float* __restrict__ We1,
                                                 const float* __restrict__ We2,
                                                 const float* __restrict__ be2) {
    extern __shared__ char smem[];
    __half* w2h = reinterpret_cast<__half*>(smem + SB_W2H);
    __half* uhi = reinterpret_cast<__half*>(smem + SB_UH);
    float* W1e_s = reinterpret_cast<float*>(smem + SB_W1E);
    float* W1r_s = reinterpret_cast<float*>(smem + SB_W1R);
    float* be2_s = reinterpret_cast<float*>(smem + SB_BE2);

    const int t = threadIdx.x;
    const int w = t >> 5, lane = t & 31;

    // stage W2^T fp16 (once per block): We2 is [k][c] -> w2h[c][k]
    for (int i = t; i < 16384; i += 512) {
        const int k = i >> 7, c = i & 127;
        w2h[c * BSTRIDE + k] = __float2half_rn(We2[i]);
    }
    for (int i = t; i < 2048; i += 512) W1e_s[i] = We1[257 * 128 + i];
    if (t < 128) {
        W1r_s[t] = We1[256 * 128 + t];
        be2_s[t] = be2[t];
    }
    __syncthreads();

    const float4 wr = *reinterpret_cast<const float4*>(W1r_s + lane * 4);

    // Phase-B tiling: 16 warps -> m16 (mt = w&7) x n64 (nh = w>>3)
    const int mt = w & 7;
    const int nh = w >> 3;
    const int g  = lane >> 2;
    const int tq = lane & 3;

    // ldmatrix lane maps
    const int rA = lane & 15;
    const int kA = (lane & 16) ? 8 : 0;
    const int rB = ((lane >> 4) & 1) * 8 + (lane & 7);
    const int kB = (lane & 8) ? 8 : 0;
    const uint32_t uhi_s = (uint32_t)__cvta_generic_to_shared(uhi);
    const uint32_t w2h_s = (uint32_t)__cvta_generic_to_shared(w2h);
    const uint32_t aoff  = (uint32_t)(((mt * 16 + rA) * BSTRIDE + kA) * 2);
    uint32_t boff[2][2];
#pragma unroll
    for (int hf = 0; hf < 2; hf++)
#pragma unroll
        for (int p = 0; p < 2; p++)
            boff[hf][p] = (uint32_t)(((nh * 64 + hf * 32 + p * 16 + rB) * BSTRIDE + kB) * 2);

    for (int tile = blockIdx.x; tile < NUM_ETILES; tile += EGRID) {
        const int e0 = tile * ETILE;
        __syncthreads();   // protect u buffer vs previous tile readers

        // ---- Phase A: 16 warps x 8 edges; u (fp16) -> smem
        {
            const int ebase = w * 8;
            const int co    = lane * 4;
            int r8 = 0, c8 = 0;
            float rad8 = 0.f;
            if (lane < 8) {
                const int eg = e0 + ebase + lane;
                r8 = g_row[eg];
                c8 = g_col[eg];
                const float dx = x[r8 * 3 + 0] - x[c8 * 3 + 0];
                const float dy = x[r8 * 3 + 1] - x[c8 * 3 + 1];
                const float dz = x[r8 * 3 + 2] - x[c8 * 3 + 2];
                rad8 = dx * dx + dy * dy + dz * dz;
            }
            float acc[8][4];
#pragma unroll
            for (int ii = 0; ii < 8; ii++) {
                const int r   = __shfl_sync(0xffffffffu, r8, ii);
                const int c   = __shfl_sync(0xffffffffu, c8, ii);
                const float rad = __shfl_sync(0xffffffffu, rad8, ii);
                const uint2 a2 = *reinterpret_cast<const uint2*>(g_hAB + (size_t)r * 256 + co);
                const uint2 b2 = *reinterpret_cast<const uint2*>(g_hAB + (size_t)c * 256 + 128 + co);
                const float2 a01 = __half22float2(*reinterpret_cast<const __half2*>(&a2.x));
                const float2 a23 = __half22float2(*reinterpret_cast<const __half2*>(&a2.y));
                const float2 b01 = __half22float2(*reinterpret_cast<const __half2*>(&b2.x));
                const float2 b23 = __half22float2(*reinterpret_cast<const __half2*>(&b2.y));
                acc[ii][0] = fmaf(rad, wr.x, a01.x + b01.x);
                acc[ii][1] = fmaf(rad, wr.y, a01.y + b01.y);
                acc[ii][2] = fmaf(rad, wr.z, a23.x + b23.x);
                acc[ii][3] = fmaf(rad, wr.w, a23.y + b23.y);
            }
#pragma unroll
            for (int jb = 0; jb < 4; jb++) {
                float4 wv[4];
#pragma unroll
                for (int q = 0; q < 4; q++)
                    wv[q] = *reinterpret_cast<const float4*>(W1e_s + (jb * 4 + q) * 128 + co);
#pragma unroll
                for (int ii = 0; ii < 8; ii++) {
                    const float4 e4 = __ldcs(reinterpret_cast<const float4*>(
                        ea + (size_t)(e0 + ebase + ii) * 16 + jb * 4));
                    const float ev[4] = {e4.x, e4.y, e4.z, e4.w};
#pragma unroll
                    for (int q = 0; q < 4; q++) {
                        acc[ii][0] = fmaf(ev[q], wv[q].x, acc[ii][0]);
                        acc[ii][1] = fmaf(ev[q], wv[q].y, acc[ii][1]);
                        acc[ii][2] = fmaf(ev[q], wv[q].z, acc[ii][2]);
                        acc[ii][3] = fmaf(ev[q], wv[q].w, acc[ii][3]);
                    }
                }
            }
#pragma unroll
            for (int ii = 0; ii < 8; ii++) {
                const int e = ebase + ii;
                __half2 hp0 = __floats2half2_rn(silu_f(acc[ii][0]), silu_f(acc[ii][1]));
                __half2 hp1 = __floats2half2_rn(silu_f(acc[ii][2]), silu_f(acc[ii][3]));
                uint2 hv;
                hv.x = *reinterpret_cast<uint32_t*>(&hp0);
                hv.y = *reinterpret_cast<uint32_t*>(&hp1);
                *reinterpret_cast<uint2*>(uhi + e * BSTRIDE + co) = hv;
            }
        }
        __syncthreads();

        // ---- Phase B: D = u_hi @ W_hi (fp16, LDSM + mma, single term)
        {
            float d[8][4];
#pragma unroll
            for (int nt = 0; nt < 8; nt++)
#pragma unroll
                for (int j = 0; j < 4; j++) d[nt][j] = 0.f;

#pragma unroll
            for (int ks = 0; ks < 8; ks++) {
                const uint32_t kb2 = ks * 32;
                uint32_t ah[4];
                ldsm4(ah, uhi_s + aoff + kb2);
#pragma unroll
                for (int hf = 0; hf < 2; hf++) {
                    uint32_t bf[2][4];
                    ldsm4(bf[0], w2h_s + boff[hf][0] + kb2);
                    ldsm4(bf[1], w2h_s + boff[hf][1] + kb2);
#pragma unroll
                    for (int p = 0; p < 2; p++)
#pragma unroll
                        for (int sub = 0; sub < 2; sub++) {
                            const int nt = hf * 4 + p * 2 + sub;
                            mma_f16(d[nt], ah[0], ah[1], ah[2], ah[3],
                                    bf[p][sub * 2], bf[p][sub * 2 + 1]);
                        }
                }
            }

            // epilogue: silu(+bias), shfl-pair, red.v4 scatter
            const int er0 = g_row[e0 + mt * 16 + g];
            const int er1 = g_row[e0 + mt * 16 + g + 8];
            const bool evenq = (tq & 1) == 0;
#pragma unroll
            for (int nt = 0; nt < 8; nt++) {
                const int col = nh * 64 + nt * 8 + 2 * tq;
                const float b0v = be2_s[col];
                const float b1v = be2_s[col + 1];
                const float v00 = silu_f(d[nt][0] + b0v);
                const float v01 = silu_f(d[nt][1] + b1v);
                const float v10 = silu_f(d[nt][2] + b0v);
                const float v11 = silu_f(d[nt][3] + b1v);
                const float p00 = __shfl_xor_sync(0xffffffffu, v00, 1);
                const float p01 = __shfl_xor_sync(0xffffffffu, v01, 1);
                const float p10 = __shfl_xor_sync(0xffffffffu, v10, 1);
                const float p11 = __shfl_xor_sync(0xffffffffu, v11, 1);
                const int colbase = nh * 64 + nt * 8 + (tq & 2) * 2;
                if (evenq) {
                    asm volatile("red.global.add.v4.f32 [%0], {%1, %2, %3, %4};"
                                 :: "l"(g_agg + (size_t)er0 * 128 + colbase),
                                    "f"(v00), "f"(v01), "f"(p00), "f"(p01) : "memory");
                } else {
                    asm volatile("red.global.add.v4.f32 [%0], {%1, %2, %3, %4};"
                                 :: "l"(g_agg + (size_t)er1 * 128 + colbase),
                                    "f"(p10), "f"(p11), "f"(v10), "f"(v11) : "memory");
                }
            }
        }
    }
}

// ---------------- k_node (launch #5): mid = silu(hn1 + agg@Wn1b); scatter to pools ----
#define NODE_SMEM_FLOATS (128 * 36 + 32)
#define NODE_SMEM_BYTES  (NODE_SMEM_FLOATS * 4)

__global__ __launch_bounds__(256) void k_node(const float* __restrict__ h,
                                              const float* __restrict__ Wn1) {
    extern __shared__ float sm[];
    float* a_s = sm;
    int*   b_s = reinterpret_cast<int*>(sm + 128 * 36);

    const int n0 = blockIdx.x * NTILE;
    const int t = threadIdx.x;
    {
        const int n  = t >> 3;
        const int k4 = t & 7;
        const int ng = n0 + n;
#pragma unroll
        for (int j = 0; j < 4; j++) {
            const int k = k4 * 16 + j * 4;
            float4 w = make_float4(0.f, 0.f, 0.f, 0.f);
            if (ng < N_NODES)
                w = *reinterpret_cast<const float4*>(g_agg + (size_t)ng * 128 + k);
            a_s[(k + 0) * 36 + n] = w.x;
            a_s[(k + 1) * 36 + n] = w.y;
            a_s[(k + 2) * 36 + n] = w.z;
            a_s[(k + 3) * 36 + n] = w.w;
        }
        if (t < 32) b_s[t] = (n0 + t < N_NODES) ? g_batch[n0 + t] : 0;
    }
    __syncthreads();

    const int cg = t & 31;
    const int ng = t >> 5;
    const int cn = cg * 4;
    float acc[4][4];
#pragma unroll
    for (int i = 0; i < 4; i++)
#pragma unroll
        for (int j = 0; j < 4; j++) acc[i][j] = 0.f;

    for (int k = 0; k < 128; k++) {
        float av[4];
#pragma unroll
        for (int i = 0; i < 4; i++) av[i] = a_s[k * 36 + ng * 4 + i];
        const float4 w = __ldg(reinterpret_cast<const float4*>(Wn1 + (128 + k) * 128 + cn));
        const float wv[4] = {w.x, w.y, w.z, w.w};
#pragma unroll
        for (int i = 0; i < 4; i++)
#pragma unroll
            for (int j = 0; j < 4; j++) acc[i][j] = fmaf(av[i], wv[j], acc[i][j]);
    }
#pragma unroll
    for (int i = 0; i < 4; i++) {
        const int n = n0 + ng * 4 + i;
        if (n < N_NODES) {
            const int b = b_s[ng * 4 + i];
            const float4 hn = *reinterpret_cast<const float4*>(g_hn1 + (size_t)n * 128 + cn);
            const float m0 = silu_f(acc[i][0] + hn.x);
            const float m1 = silu_f(acc[i][1] + hn.y);
            const float m2 = silu_f(acc[i][2] + hn.z);
            const float m3 = silu_f(acc[i][3] + hn.w);
            asm volatile("red.global.add.v4.f32 [%0], {%1, %2, %3, %4};"
                         :: "l"(g_poolm + b * 128 + cn), "f"(m0), "f"(m1), "f"(m2), "f"(m3)
                         : "memory");
            const float4 hv = *reinterpret_cast<const float4*>(h + (size_t)n * 128 + cn);
            asm volatile("red.global.add.v4.f32 [%0], {%1, %2, %3, %4};"
                         :: "l"(g_pool + b * 128 + cn), "f"(hv.x), "f"(hv.y), "f"(hv.z), "f"(hv.w)
                         : "memory");
        }
    }
    if (t < 32 && n0 + t < N_NODES) atomicAdd(&g_cnt[b_s[t]], 1.0f);
}

// ---------------- k_pool_final (launch #6) ----------------
__global__ void k_pool_final(const float* __restrict__ Wn2,
                             const float* __restrict__ bn2,
                             float* __restrict__ out) {
    __shared__ float pm[128];
    const int g = blockIdx.x;
    const int c = threadIdx.x;
    pm[c] = g_poolm[g * 128 + c];
    __syncthreads();
    float dot = 0.f;
    for (int k = 0; k < 128; k++)
        dot = fmaf(pm[k], __ldg(Wn2 + k * 128 + c), dot);
    const float cnt = g_cnt[g];
    const float s = g_pool[g * 128 + c] + dot + cnt * __ldg(bn2 + c);
    out[g * 128 + c] = s / fmaxf(cnt, 1.0f);
}

// ---------------- launcher ----------------
extern "C" void kernel_launch(void* const* d_in, const int* in_sizes, int n_in,
                              void* d_out, int out_size) {
    const float* h   = (const float*)d_in[0];
    const void*  ei  = d_in[1];
    const float* x   = (const float*)d_in[2];
    const float* ea  = (const float*)d_in[3];
    const void*  bat = d_in[4];
    const float* We1 = (const float*)d_in[5];
    const float* be1 = (const float*)d_in[6];
    const float* We2 = (const float*)d_in[7];
    const float* be2 = (const float*)d_in[8];
    const float* Wn1 = (const float*)d_in[9];
    const float* bn1 = (const float*)d_in[10];
    const float* Wn2 = (const float*)d_in[11];
    const float* bn2 = (const float*)d_in[12];
    float* out = (float*)d_out;

    cudaFuncSetAttribute(k_pre,  cudaFuncAttributeMaxDynamicSharedMemorySize, PRE_SMEM_BYTES);
    cudaFuncSetAttribute(k_edge, cudaFuncAttributeMaxDynamicSharedMemorySize, EDGE_SMEM_BYTES);
    cudaFuncSetAttribute(k_node, cudaFuncAttributeMaxDynamicSharedMemorySize, NODE_SMEM_BYTES);

    k_init<<<(N_NODES * HID / 4 + 255) / 256, 256>>>(ei);                       // #1
    k_cvt_idx<<<(N_EDGES + 255) / 256, 256>>>(ei, bat);                         // #2
    k_pre<<<PGRID, 512, PRE_SMEM_BYTES>>>(h, We1, be1, Wn1, bn1);               // #3
    k_edge<<<EGRID, 512, EDGE_SMEM_BYTES>>>(x, ea, We1, We2, be2);              // #4 (ncu slot)
    k_node<<<(N_NODES + NTILE - 1) / NTILE, 256, NODE_SMEM_BYTES>>>(h, Wn1);    // #5
    k_pool_final<<<N_GRAPHS, HID>>>(Wn2, bn2, out);                             // #6
}

// round 16
// speedup vs baseline: 1.2517x; 1.0692x over previous
#include <cuda_runtime.h>
#include <cuda_fp16.h>
#include <cstdint>

#define N_NODES  50000
#define N_EDGES  800000
#define HID      128
#define EDGE_D   16
#define N_GRAPHS 64

#define ETILE 128
#define NTILE 32
#define NUM_ETILES (N_EDGES / ETILE)
#define NUM_PTILES ((N_NODES + 31) / 32)
#define EGRID 304
#define PGRID 152

// ---------------- device scratch (static, no allocation) ----------------
__device__ __half g_hAB[(size_t)N_NODES * 256];  // hA | hB  fp16 (25.6 MB)
__device__ float g_hn1[(size_t)N_NODES * 128];   // h @ Wn1a + bn1 (25.6 MB)
__device__ float g_agg[(size_t)N_NODES * HID];   // scatter target (25.6 MB)
__device__ float g_pool[N_GRAPHS * HID];         // sum of h per graph
__device__ float g_poolm[N_GRAPHS * HID];        // sum of mid per graph
__device__ float g_cnt[N_GRAPHS];
__device__ int   g_row[N_EDGES];
__device__ int   g_col[N_EDGES];
__device__ int   g_batch[N_NODES];
__device__ int   g_is64;

__device__ __forceinline__ float silu_f(float v) {
    return __fdividef(v, 1.0f + __expf(-v));
}

// fp16 mma m16n8k16
__device__ __forceinline__ void mma_f16(float* d, uint32_t a0, uint32_t a1,
                                        uint32_t a2, uint32_t a3,
                                        uint32_t b0, uint32_t b1) {
    asm volatile(
        "mma.sync.aligned.m16n8k16.row.col.f32.f16.f16.f32 "
        "{%0,%1,%2,%3}, {%4,%5,%6,%7}, {%8,%9}, {%0,%1,%2,%3};"
        : "+f"(d[0]), "+f"(d[1]), "+f"(d[2]), "+f"(d[3])
        : "r"(a0), "r"(a1), "r"(a2), "r"(a3), "r"(b0), "r"(b1));
}

__device__ __forceinline__ void ldsm4(uint32_t* r, uint32_t addr) {
    asm volatile("ldmatrix.sync.aligned.m8n8.x4.shared.b16 {%0,%1,%2,%3}, [%4];"
                 : "=r"(r[0]), "=r"(r[1]), "=r"(r[2]), "=r"(r[3]) : "r"(addr));
}

// ---------------- init (launch #1) ----------------
__global__ void k_init(const void* __restrict__ ei) {
    const int i = blockIdx.x * blockDim.x + threadIdx.x;
    if (i < (N_NODES * HID) / 4)
        reinterpret_cast<float4*>(g_agg)[i] = make_float4(0.f, 0.f, 0.f, 0.f);
    if (i < N_GRAPHS * HID) { g_pool[i] = 0.f; g_poolm[i] = 0.f; }
    if (i < N_GRAPHS)       g_cnt[i] = 0.f;
    if (i == 0) {
        const unsigned int* p = (const unsigned int*)ei;
        int is64 = 1;
        for (int j = 0; j < 16; j++) if (p[2 * j + 1] != 0u) is64 = 0;
        g_is64 = is64;
    }
}

// ---------------- index conversion (launch #2) ----------------
__global__ void k_cvt_idx(const void* __restrict__ ei, const void* __restrict__ batch) {
    const int i = blockIdx.x * blockDim.x + threadIdx.x;
    const bool is64 = (g_is64 != 0);
    if (i < N_EDGES) {
        if (is64) {
            const long long* p = (const long long*)ei;
            g_row[i] = (int)p[i];
            g_col[i] = (int)p[N_EDGES + i];
        } else {
            const int* p = (const int*)ei;
            g_row[i] = p[i];
            g_col[i] = p[N_EDGES + i];
        }
    }
    if (i < N_NODES) {
        if (is64) g_batch[i] = (int)((const long long*)batch)[i];
        else      g_batch[i] = ((const int*)batch)[i];
    }
}

// ---------------- k_pre (launch #3): persistent fp16 single-term pre-GEMM ------------
// D[n][c] = h[n] @ [We1a | We1b | Wn1a][.,c] (+be1 c<128, +bn1 c>=256), fp16 mma.
#define BSTRIDE 136   // b16 elements per row (272 B) -> conflict-free fragments

#define PB_BH   0                  // 384x136 fp16 = 104448 B
#define PB_AH   104448             // 32x136 fp16 = 8704 B
#define PB_BIAS 113152             // 384 f32 = 1536 B
#define PRE_SMEM_BYTES 114688

__global__ __launch_bounds__(512, 1) void k_pre(const float* __restrict__ h,
                                                const float* __restrict__ We1,
                                                const float* __restrict__ be1,
                                                const float* __restrict__ Wn1,
                                                const float* __restrict__ bn1) {
    extern __shared__ char smem[];
    __half* Bh = reinterpret_cast<__half*>(smem + PB_BH);
    __half* Ah = reinterpret_cast<__half*>(smem + PB_AH);
    float* bias_s = reinterpret_cast<float*>(smem + PB_BIAS);

    const int t = threadIdx.x;
    const int w = t >> 5, lane = t & 31;

    for (int i = t; i < 384 * 128; i += 512) {
        const int c = i >> 7, k = i & 127;
        float v;
        if (c < 128)       v = We1[k * 128 + c];
        else if (c < 256)  v = We1[(128 + k) * 128 + (c - 128)];
        else               v = Wn1[k * 128 + (c - 256)];
        Bh[c * BSTRIDE + k] = __float2half_rn(v);
    }
    for (int i = t; i < 384; i += 512) {
        float b = 0.f;
        if (i < 128)      b = be1[i];
        else if (i >= 256) b = bn1[i - 256];
        bias_s[i] = b;
    }
    __syncthreads();

    const int mt = w & 1;        // 2 m-tiles of 16 nodes
    const int nb = w >> 1;       // 8 n-tiles of 48 cols
    const int g  = lane >> 2;
    const int tq = lane & 3;

    for (int tile = blockIdx.x; tile < NUM_PTILES; tile += PGRID) {
        const int n0 = tile * 32;
        __syncthreads();
        for (int idx = t; idx < 1024; idx += 512) {
            const int n = idx >> 5, kq = idx & 31;
            float4 v = make_float4(0.f, 0.f, 0.f, 0.f);
            if (n0 + n < N_NODES)
                v = *reinterpret_cast<const float4*>(h + (size_t)(n0 + n) * 128 + kq * 4);
            __half2 p0 = __floats2half2_rn(v.x, v.y);
            __half2 p1 = __floats2half2_rn(v.z, v.w);
            uint2 hv;
            hv.x = *reinterpret_cast<uint32_t*>(&p0);
            hv.y = *reinterpret_cast<uint32_t*>(&p1);
            *reinterpret_cast<uint2*>(Ah + n * BSTRIDE + kq * 4) = hv;
        }
        __syncthreads();

        float d[6][4];
#pragma unroll
        for (int nt = 0; nt < 6; nt++)
#pragma unroll
            for (int j = 0; j < 4; j++) d[nt][j] = 0.f;

        const int arow = mt * 16 + g;
#pragma unroll
        for (int ks = 0; ks < 8; ks++) {
            const int kb = ks * 16;
            const __half* Ap = Ah + arow * BSTRIDE + 2 * tq + kb;
            const uint32_t a0 = *reinterpret_cast<const uint32_t*>(Ap);
            const uint32_t a1 = *reinterpret_cast<const uint32_t*>(Ap + 8 * BSTRIDE);
            const uint32_t a2 = *reinterpret_cast<const uint32_t*>(Ap + 8);
            const uint32_t a3 = *reinterpret_cast<const uint32_t*>(Ap + 8 * BSTRIDE + 8);
#pragma unroll
            for (int nt = 0; nt < 6; nt++) {
                const __half* Bp = Bh + (nb * 48 + nt * 8 + g) * BSTRIDE + 2 * tq + kb;
                const uint32_t b0 = *reinterpret_cast<const uint32_t*>(Bp);
                const uint32_t b1 = *reinterpret_cast<const uint32_t*>(Bp + 8);
                mma_f16(d[nt], a0, a1, a2, a3, b0, b1);
            }
        }

        const int r0 = n0 + mt * 16 + g;
        const int r1 = r0 + 8;
#pragma unroll
        for (int nt = 0; nt < 6; nt++) {
            const int col = nb * 48 + nt * 8 + 2 * tq;
            const float b0 = bias_s[col], b1 = bias_s[col + 1];
            const float v00 = d[nt][0] + b0, v01 = d[nt][1] + b1;
            const float v10 = d[nt][2] + b0, v11 = d[nt][3] + b1;
            if (col < 256) {
                const __half2 h0 = __floats2half2_rn(v00, v01);
                const __half2 h1 = __floats2half2_rn(v10, v11);
                if (r0 < N_NODES) *reinterpret_cast<__half2*>(g_hAB + (size_t)r0 * 256 + col) = h0;
                if (r1 < N_NODES) *reinterpret_cast<__half2*>(g_hAB + (size_t)r1 * 256 + col) = h1;
            } else {
                if (r0 < N_NODES)
                    *reinterpret_cast<float2*>(g_hn1 + (size_t)r0 * 128 + col - 256) = make_float2(v00, v01);
                if (r1 < N_NODES)
                    *reinterpret_cast<float2*>(g_hn1 + (size_t)r1 * 128 + col - 256) = make_float2(v10, v11);
            }
        }
    }
}

// ---------------- fused edge kernel (launch #4; 2 CTAs/SM, m32xn32, fp16 1-term) ----
#define SB_W2H   0                 // 128x136 fp16 = 34816 B (W2^T)
#define SB_UH    34816             // 34816 B  u (fp16)
#define SB_W1E   69632             // 2048 f32 = 8192 B
#define SB_W1R   77824             // 512 B
#define SB_BE2   78336             // 512 B
#define EDGE_SMEM_BYTES 78848

__global__ __launch_bounds__(512, 2) void k_edge(const float* __restrict__ x,
                                                 const float* __restrict__ ea,
                                                 const float* __restrict__ We1,
                                                 const float* __restrict__ We2,
                                                 const float* __restrict__ be2) {
    extern __shared__ char smem[];
    __half* w2h = reinterpret_cast<__half*>(smem + SB_W2H);
    __half* uhi = reinterpret_cast<__half*>(smem + SB_UH);
    float* W1e_s = reinterpret_cast<float*>(smem + SB_W1E);
    float* W1r_s = reinterpret_cast<float*>(smem + SB_W1R);
    float* be2_s = reinterpret_cast<float*>(smem + SB_BE2);

    const int t = threadIdx.x;
    const int w = t >> 5, lane = t & 31;

    for (int i = t; i < 16384; i += 512) {
        const int k = i >> 7, c = i & 127;
        w2h[c * BSTRIDE + k] = __float2half_rn(We2[i]);
    }
    for (int i = t; i < 2048; i += 512) W1e_s[i] = We1[257 * 128 + i];
    if (t < 128) {
        W1r_s[t] = We1[256 * 128 + t];
        be2_s[t] = be2[t];
    }
    __syncthreads();

    const float4 wr = *reinterpret_cast<const float4*>(W1r_s + lane * 4);

    // Phase-B tiling: 16 warps -> m32 (mt2 = w&3) x n32 (nq2 = w>>2)
    const int mt2 = w & 3;
    const int nq2 = w >> 2;
    const int g   = lane >> 2;
    const int tq  = lane & 3;

    // ldmatrix lane maps
    const int rA = lane & 15;
    const int kA = (lane & 16) ? 8 : 0;
    const int rB = ((lane >> 4) & 1) * 8 + (lane & 7);
    const int kB = (lane & 8) ? 8 : 0;
    const uint32_t uhi_s = (uint32_t)__cvta_generic_to_shared(uhi);
    const uint32_t w2h_s = (uint32_t)__cvta_generic_to_shared(w2h);
    const uint32_t aoff  = (uint32_t)(((mt2 * 32 + rA) * BSTRIDE + kA) * 2);
    const uint32_t boff  = (uint32_t)(((nq2 * 32 + rB) * BSTRIDE + kB) * 2);
    const uint32_t mstep = 16 * BSTRIDE * 2;

    for (int tile = blockIdx.x; tile < NUM_ETILES; tile += EGRID) {
        const int e0 = tile * ETILE;
        __syncthreads();   // protect u buffer vs previous tile readers

        // ---- Phase A: 16 warps x 8 edges; u (fp16) -> smem
        {
            const int ebase = w * 8;
            const int co    = lane * 4;
            int r8 = 0, c8 = 0;
            float rad8 = 0.f;
            if (lane < 8) {
                const int eg = e0 + ebase + lane;
                r8 = g_row[eg];
                c8 = g_col[eg];
                const float dx = x[r8 * 3 + 0] - x[c8 * 3 + 0];
                const float dy = x[r8 * 3 + 1] - x[c8 * 3 + 1];
                const float dz = x[r8 * 3 + 2] - x[c8 * 3 + 2];
                rad8 = dx * dx + dy * dy + dz * dz;
            }
            float acc[8][4];
#pragma unroll
            for (int ii = 0; ii < 8; ii++) {
                const int r   = __shfl_sync(0xffffffffu, r8, ii);
                const int c   = __shfl_sync(0xffffffffu, c8, ii);
                const float rad = __shfl_sync(0xffffffffu, rad8, ii);
                const uint2 a2 = *reinterpret_cast<const uint2*>(g_hAB + (size_t)r * 256 + co);
                const uint2 b2 = *reinterpret_cast<const uint2*>(g_hAB + (size_t)c * 256 + 128 + co);
                const float2 a01 = __half22float2(*reinterpret_cast<const __half2*>(&a2.x));
                const float2 a23 = __half22float2(*reinterpret_cast<const __half2*>(&a2.y));
                const float2 b01 = __half22float2(*reinterpret_cast<const __half2*>(&b2.x));
                const float2 b23 = __half22float2(*reinterpret_cast<const __half2*>(&b2.y));
                acc[ii][0] = fmaf(rad, wr.x, a01.x + b01.x);
                acc[ii][1] = fmaf(rad, wr.y, a01.y + b01.y);
                acc[ii][2] = fmaf(rad, wr.z, a23.x + b23.x);
                acc[ii][3] = fmaf(rad, wr.w, a23.y + b23.y);
            }
#pragma unroll
            for (int jb = 0; jb < 4; jb++) {
                float4 wv[4];
#pragma unroll
                for (int q = 0; q < 4; q++)
                    wv[q] = *reinterpret_cast<const float4*>(W1e_s + (jb * 4 + q) * 128 + co);
#pragma unroll
                for (int ii = 0; ii < 8; ii++) {
                    const float4 e4 = __ldcs(reinterpret_cast<const float4*>(
                        ea + (size_t)(e0 + ebase + ii) * 16 + jb * 4));
                    const float ev[4] = {e4.x, e4.y, e4.z, e4.w};
#pragma unroll
                    for (int q = 0; q < 4; q++) {
                        acc[ii][0] = fmaf(ev[q], wv[q].x, acc[ii][0]);
                        acc[ii][1] = fmaf(ev[q], wv[q].y, acc[ii][1]);
                        acc[ii][2] = fmaf(ev[q], wv[q].z, acc[ii][2]);
                        acc[ii][3] = fmaf(ev[q], wv[q].w, acc[ii][3]);
                    }
                }
            }
#pragma unroll
            for (int ii = 0; ii < 8; ii++) {
                const int e = ebase + ii;
                __half2 hp0 = __floats2half2_rn(silu_f(acc[ii][0]), silu_f(acc[ii][1]));
                __half2 hp1 = __floats2half2_rn(silu_f(acc[ii][2]), silu_f(acc[ii][3]));
                uint2 hv;
                hv.x = *reinterpret_cast<uint32_t*>(&hp0);
                hv.y = *reinterpret_cast<uint32_t*>(&hp1);
                *reinterpret_cast<uint2*>(uhi + e * BSTRIDE + co) = hv;
            }
        }
        __syncthreads();

        // ---- Phase B: D = u @ W2 (fp16 mma, m32xn32 warp tile)
        {
            float d[2][4][4];
#pragma unroll
            for (int mi = 0; mi < 2; mi++)
#pragma unroll
                for (int nt = 0; nt < 4; nt++)
#pragma unroll
                    for (int j = 0; j < 4; j++) d[mi][nt][j] = 0.f;

#pragma unroll
            for (int ks = 0; ks < 8; ks++) {
                const uint32_t kb2 = ks * 32;
                uint32_t ah[2][4], bf[2][4];
                ldsm4(ah[0], uhi_s + aoff + kb2);
                ldsm4(ah[1], uhi_s + aoff + mstep + kb2);
                ldsm4(bf[0], w2h_s + boff + kb2);
                ldsm4(bf[1], w2h_s + boff + mstep + kb2);
#pragma unroll
                for (int p = 0; p < 2; p++)
#pragma unroll
                    for (int sub = 0; sub < 2; sub++) {
                        const int nt = p * 2 + sub;
                        const uint32_t b0 = bf[p][sub * 2], b1 = bf[p][sub * 2 + 1];
#pragma unroll
                        for (int mi = 0; mi < 2; mi++)
                            mma_f16(d[mi][nt], ah[mi][0], ah[mi][1], ah[mi][2], ah[mi][3], b0, b1);
                    }
            }

            // epilogue: silu(+bias), shfl-pair, red.v4 scatter
            const bool evenq = (tq & 1) == 0;
#pragma unroll
            for (int mi = 0; mi < 2; mi++) {
                const int er0 = g_row[e0 + mt2 * 32 + mi * 16 + g];
                const int er1 = g_row[e0 + mt2 * 32 + mi * 16 + g + 8];
#pragma unroll
                for (int nt = 0; nt < 4; nt++) {
                    const int col = nq2 * 32 + nt * 8 + 2 * tq;
                    const float b0v = be2_s[col];
                    const float b1v = be2_s[col + 1];
                    const float v00 = silu_f(d[mi][nt][0] + b0v);
                    const float v01 = silu_f(d[mi][nt][1] + b1v);
                    const float v10 = silu_f(d[mi][nt][2] + b0v);
                    const float v11 = silu_f(d[mi][nt][3] + b1v);
                    const float p00 = __shfl_xor_sync(0xffffffffu, v00, 1);
                    const float p01 = __shfl_xor_sync(0xffffffffu, v01, 1);
                    const float p10 = __shfl_xor_sync(0xffffffffu, v10, 1);
                    const float p11 = __shfl_xor_sync(0xffffffffu, v11, 1);
                    const int colbase = nq2 * 32 + nt * 8 + (tq & 2) * 2;
                    if (evenq) {
                        asm volatile("red.global.add.v4.f32 [%0], {%1, %2, %3, %4};"
                                     :: "l"(g_agg + (size_t)er0 * 128 + colbase),
                                        "f"(v00), "f"(v01), "f"(p00), "f"(p01) : "memory");
                    } else {
                        asm volatile("red.global.add.v4.f32 [%0], {%1, %2, %3, %4};"
                                     :: "l"(g_agg + (size_t)er1 * 128 + colbase),
                                        "f"(p10), "f"(p11), "f"(v10), "f"(v11) : "memory");
                    }
                }
            }
        }
    }
}

// ---------------- k_node (launch #5): mid = silu(hn1 + agg@Wn1b); scatter to pools ----
#define NODE_SMEM_FLOATS (128 * 36 + 32)
#define NODE_SMEM_BYTES  (NODE_SMEM_FLOATS * 4)

__global__ __launch_bounds__(256) void k_node(const float* __restrict__ h,
                                              const float* __restrict__ Wn1) {
    extern __shared__ float sm[];
    float* a_s = sm;
    int*   b_s = reinterpret_cast<int*>(sm + 128 * 36);

    const int n0 = blockIdx.x * NTILE;
    const int t = threadIdx.x;
    {
        const int n  = t >> 3;
        const int k4 = t & 7;
        const int ng = n0 + n;
#pragma unroll
        for (int j = 0; j < 4; j++) {
            const int k = k4 * 16 + j * 4;
            float4 w = make_float4(0.f, 0.f, 0.f, 0.f);
            if (ng < N_NODES)
                w = *reinterpret_cast<const float4*>(g_agg + (size_t)ng * 128 + k);
            a_s[(k + 0) * 36 + n] = w.x;
            a_s[(k + 1) * 36 + n] = w.y;
            a_s[(k + 2) * 36 + n] = w.z;
            a_s[(k + 3) * 36 + n] = w.w;
        }
        if (t < 32) b_s[t] = (n0 + t < N_NODES) ? g_batch[n0 + t] : 0;
    }
    __syncthreads();

    const int cg = t & 31;
    const int ng = t >> 5;
    const int cn = cg * 4;
    float acc[4][4];
#pragma unroll
    for (int i = 0; i < 4; i++)
#pragma unroll
        for (int j = 0; j < 4; j++) acc[i][j] = 0.f;

    for (int k = 0; k < 128; k++) {
        float av[4];
#pragma unroll
        for (int i = 0; i < 4; i++) av[i] = a_s[k * 36 + ng * 4 + i];
        const float4 w = __ldg(reinterpret_cast<const float4*>(Wn1 + (128 + k) * 128 + cn));
        const float wv[4] = {w.x, w.y, w.z, w.w};
#pragma unroll
        for (int i = 0; i < 4; i++)
#pragma unroll
            for (int j = 0; j < 4; j++) acc[i][j] = fmaf(av[i], wv[j], acc[i][j]);
    }
#pragma unroll
    for (int i = 0; i < 4; i++) {
        const int n = n0 + ng * 4 + i;
        if (n < N_NODES) {
            const int b = b_s[ng * 4 + i];
            const float4 hn = *reinterpret_cast<const float4*>(g_hn1 + (size_t)n * 128 + cn);
            const float m0 = silu_f(acc[i][0] + hn.x);
            const float m1 = silu_f(acc[i][1] + hn.y);
            const float m2 = silu_f(acc[i][2] + hn.z);
            const float m3 = silu_f(acc[i][3] + hn.w);
            asm volatile("red.global.add.v4.f32 [%0], {%1, %2, %3, %4};"
                         :: "l"(g_poolm + b * 128 + cn), "f"(m0), "f"(m1), "f"(m2), "f"(m3)
                         : "memory");
            const float4 hv = *reinterpret_cast<const float4*>(h + (size_t)n * 128 + cn);
            asm volatile("red.global.add.v4.f32 [%0], {%1, %2, %3, %4};"
                         :: "l"(g_pool + b * 128 + cn), "f"(hv.x), "f"(hv.y), "f"(hv.z), "f"(hv.w)
                         : "memory");
        }
    }
    if (t < 32 && n0 + t < N_NODES) atomicAdd(&g_cnt[b_s[t]], 1.0f);
}

// ---------------- k_pool_final (launch #6) ----------------
__global__ void k_pool_final(const float* __restrict__ Wn2,
                             const float* __restrict__ bn2,
                             float* __restrict__ out) {
    __shared__ float pm[128];
    const int g = blockIdx.x;
    const int c = threadIdx.x;
    pm[c] = g_poolm[g * 128 + c];
    __syncthreads();
    float dot = 0.f;
    for (int k = 0; k < 128; k++)
        dot = fmaf(pm[k], __ldg(Wn2 + k * 128 + c), dot);
    const float cnt = g_cnt[g];
    const float s = g_pool[g * 128 + c] + dot + cnt * __ldg(bn2 + c);
    out[g * 128 + c] = s / fmaxf(cnt, 1.0f);
}

// ---------------- launcher ----------------
extern "C" void kernel_launch(void* const* d_in, const int* in_sizes, int n_in,
                              void* d_out, int out_size) {
    const float* h   = (const float*)d_in[0];
    const void*  ei  = d_in[1];
    const float* x   = (const float*)d_in[2];
    const float* ea  = (const float*)d_in[3];
    const void*  bat = d_in[4];
    const float* We1 = (const float*)d_in[5];
    const float* be1 = (const float*)d_in[6];
    const float* We2 = (const float*)d_in[7];
    const float* be2 = (const float*)d_in[8];
    const float* Wn1 = (const float*)d_in[9];
    const float* bn1 = (const float*)d_in[10];
    const float* Wn2 = (const float*)d_in[11];
    const float* bn2 = (const float*)d_in[12];
    float* out = (float*)d_out;

    cudaFuncSetAttribute(k_pre,  cudaFuncAttributeMaxDynamicSharedMemorySize, PRE_SMEM_BYTES);
    cudaFuncSetAttribute(k_edge, cudaFuncAttributeMaxDynamicSharedMemorySize, EDGE_SMEM_BYTES);
    cudaFuncSetAttribute(k_node, cudaFuncAttributeMaxDynamicSharedMemorySize, NODE_SMEM_BYTES);

    k_init<<<(N_NODES * HID / 4 + 255) / 256, 256>>>(ei);                       // #1
    k_cvt_idx<<<(N_EDGES + 255) / 256, 256>>>(ei, bat);                         // #2
    k_pre<<<PGRID, 512, PRE_SMEM_BYTES>>>(h, We1, be1, Wn1, bn1);               // #3
    k_edge<<<EGRID, 512, EDGE_SMEM_BYTES>>>(x, ea, We1, We2, be2);              // #4 (ncu slot)
    k_node<<<(N_NODES + NTILE - 1) / NTILE, 256, NODE_SMEM_BYTES>>>(h, Wn1);    // #5
    k_pool_final<<<N_GRAPHS, HID>>>(Wn2, bn2, out);                             // #6
}

// round 17
// speedup vs baseline: 1.3105x; 1.0469x over previous
#include <cuda_runtime.h>
#include <cuda_fp16.h>
#include <cstdint>

#define N_NODES  50000
#define N_EDGES  800000
#define HID      128
#define EDGE_D   16
#define N_GRAPHS 64

#define ETILE 128
#define NTILE 32
#define NUM_ETILES (N_EDGES / ETILE)
#define NUM_PTILES ((N_NODES + 31) / 32)
#define EGRID 304
#define PGRID 152
#define NGRID 304

// ---------------- device scratch (static, no allocation) ----------------
__device__ __half g_hAB[(size_t)N_NODES * 256];  // hA | hB  fp16 (25.6 MB)
__device__ float g_hn1[(size_t)N_NODES * 128];   // h @ Wn1a + bn1 (25.6 MB)
__device__ float g_agg[(size_t)N_NODES * HID];   // scatter target (25.6 MB)
__device__ float g_pool[N_GRAPHS * HID];         // sum of h per graph
__device__ float g_poolm[N_GRAPHS * HID];        // sum of mid per graph
__device__ float g_cnt[N_GRAPHS];
__device__ int   g_row[N_EDGES];
__device__ int   g_col[N_EDGES];
__device__ int   g_batch[N_NODES];
__device__ int   g_is64;

__device__ __forceinline__ float silu_f(float v) {
    return __fdividef(v, 1.0f + __expf(-v));
}

// fp16 mma m16n8k16
__device__ __forceinline__ void mma_f16(float* d, uint32_t a0, uint32_t a1,
                                        uint32_t a2, uint32_t a3,
                                        uint32_t b0, uint32_t b1) {
    asm volatile(
        "mma.sync.aligned.m16n8k16.row.col.f32.f16.f16.f32 "
        "{%0,%1,%2,%3}, {%4,%5,%6,%7}, {%8,%9}, {%0,%1,%2,%3};"
        : "+f"(d[0]), "+f"(d[1]), "+f"(d[2]), "+f"(d[3])
        : "r"(a0), "r"(a1), "r"(a2), "r"(a3), "r"(b0), "r"(b1));
}

__device__ __forceinline__ void ldsm4(uint32_t* r, uint32_t addr) {
    asm volatile("ldmatrix.sync.aligned.m8n8.x4.shared.b16 {%0,%1,%2,%3}, [%4];"
                 : "=r"(r[0]), "=r"(r[1]), "=r"(r[2]), "=r"(r[3]) : "r"(addr));
}

// ---------------- init (launch #1) ----------------
__global__ void k_init(const void* __restrict__ ei) {
    const int i = blockIdx.x * blockDim.x + threadIdx.x;
    if (i < (N_NODES * HID) / 4)
        reinterpret_cast<float4*>(g_agg)[i] = make_float4(0.f, 0.f, 0.f, 0.f);
    if (i < N_GRAPHS * HID) { g_pool[i] = 0.f; g_poolm[i] = 0.f; }
    if (i < N_GRAPHS)       g_cnt[i] = 0.f;
    if (i == 0) {
        const unsigned int* p = (const unsigned int*)ei;
        int is64 = 1;
        for (int j = 0; j < 16; j++) if (p[2 * j + 1] != 0u) is64 = 0;
        g_is64 = is64;
    }
}

// ---------------- index conversion (launch #2) ----------------
__global__ void k_cvt_idx(const void* __restrict__ ei, const void* __restrict__ batch) {
    const int i = blockIdx.x * blockDim.x + threadIdx.x;
    const bool is64 = (g_is64 != 0);
    if (i < N_EDGES) {
        if (is64) {
            const long long* p = (const long long*)ei;
            g_row[i] = (int)p[i];
            g_col[i] = (int)p[N_EDGES + i];
        } else {
            const int* p = (const int*)ei;
            g_row[i] = p[i];
            g_col[i] = p[N_EDGES + i];
        }
    }
    if (i < N_NODES) {
        if (is64) g_batch[i] = (int)((const long long*)batch)[i];
        else      g_batch[i] = ((const int*)batch)[i];
    }
}

// ---------------- k_pre (launch #3): persistent fp16 single-term pre-GEMM ------------
#define BSTRIDE 136   // b16 elements per row (272 B) -> conflict-free fragments

#define PB_BH   0                  // 384x136 fp16 = 104448 B
#define PB_AH   104448             // 32x136 fp16 = 8704 B
#define PB_BIAS 113152             // 384 f32 = 1536 B
#define PRE_SMEM_BYTES 114688

__global__ __launch_bounds__(512, 1) void k_pre(const float* __restrict__ h,
                                                const float* __restrict__ We1,
                                                const float* __restrict__ be1,
                                                const float* __restrict__ Wn1,
                                                const float* __restrict__ bn1) {
    extern __shared__ char smem[];
    __half* Bh = reinterpret_cast<__half*>(smem + PB_BH);
    __half* Ah = reinterpret_cast<__half*>(smem + PB_AH);
    float* bias_s = reinterpret_cast<float*>(smem + PB_BIAS);

    const int t = threadIdx.x;
    const int w = t >> 5, lane = t & 31;

    for (int i = t; i < 384 * 128; i += 512) {
        const int c = i >> 7, k = i & 127;
        float v;
        if (c < 128)       v = We1[k * 128 + c];
        else if (c < 256)  v = We1[(128 + k) * 128 + (c - 128)];
        else               v = Wn1[k * 128 + (c - 256)];
        Bh[c * BSTRIDE + k] = __float2half_rn(v);
    }
    for (int i = t; i < 384; i += 512) {
        float b = 0.f;
        if (i < 128)      b = be1[i];
        else if (i >= 256) b = bn1[i - 256];
        bias_s[i] = b;
    }
    __syncthreads();

    const int mt = w & 1;
    const int nb = w >> 1;
    const int g  = lane >> 2;
    const int tq = lane & 3;

    for (int tile = blockIdx.x; tile < NUM_PTILES; tile += PGRID) {
        const int n0 = tile * 32;
        __syncthreads();
        for (int idx = t; idx < 1024; idx += 512) {
            const int n = idx >> 5, kq = idx & 31;
            float4 v = make_float4(0.f, 0.f, 0.f, 0.f);
            if (n0 + n < N_NODES)
                v = *reinterpret_cast<const float4*>(h + (size_t)(n0 + n) * 128 + kq * 4);
            __half2 p0 = __floats2half2_rn(v.x, v.y);
            __half2 p1 = __floats2half2_rn(v.z, v.w);
            uint2 hv;
            hv.x = *reinterpret_cast<uint32_t*>(&p0);
            hv.y = *reinterpret_cast<uint32_t*>(&p1);
            *reinterpret_cast<uint2*>(Ah + n * BSTRIDE + kq * 4) = hv;
        }
        __syncthreads();

        float d[6][4];
#pragma unroll
        for (int nt = 0; nt < 6; nt++)
#pragma unroll
            for (int j = 0; j < 4; j++) d[nt][j] = 0.f;

        const int arow = mt * 16 + g;
#pragma unroll
        for (int ks = 0; ks < 8; ks++) {
            const int kb = ks * 16;
            const __half* Ap = Ah + arow * BSTRIDE + 2 * tq + kb;
            const uint32_t a0 = *reinterpret_cast<const uint32_t*>(Ap);
            const uint32_t a1 = *reinterpret_cast<const uint32_t*>(Ap + 8 * BSTRIDE);
            const uint32_t a2 = *reinterpret_cast<const uint32_t*>(Ap + 8);
            const uint32_t a3 = *reinterpret_cast<const uint32_t*>(Ap + 8 * BSTRIDE + 8);
#pragma unroll
            for (int nt = 0; nt < 6; nt++) {
                const __half* Bp = Bh + (nb * 48 + nt * 8 + g) * BSTRIDE + 2 * tq + kb;
                const uint32_t b0 = *reinterpret_cast<const uint32_t*>(Bp);
                const uint32_t b1 = *reinterpret_cast<const uint32_t*>(Bp + 8);
                mma_f16(d[nt], a0, a1, a2, a3, b0, b1);
            }
        }

        const int r0 = n0 + mt * 16 + g;
        const int r1 = r0 + 8;
#pragma unroll
        for (int nt = 0; nt < 6; nt++) {
            const int col = nb * 48 + nt * 8 + 2 * tq;
            const float b0 = bias_s[col], b1 = bias_s[col + 1];
            const float v00 = d[nt][0] + b0, v01 = d[nt][1] + b1;
            const float v10 = d[nt][2] + b0, v11 = d[nt][3] + b1;
            if (col < 256) {
                const __half2 h0 = __floats2half2_rn(v00, v01);
                const __half2 h1 = __floats2half2_rn(v10, v11);
                if (r0 < N_NODES) *reinterpret_cast<__half2*>(g_hAB + (size_t)r0 * 256 + col) = h0;
                if (r1 < N_NODES) *reinterpret_cast<__half2*>(g_hAB + (size_t)r1 * 256 + col) = h1;
            } else {
                if (r0 < N_NODES)
                    *reinterpret_cast<float2*>(g_hn1 + (size_t)r0 * 128 + col - 256) = make_float2(v00, v01);
                if (r1 < N_NODES)
                    *reinterpret_cast<float2*>(g_hn1 + (size_t)r1 * 128 + col - 256) = make_float2(v10, v11);
            }
        }
    }
}

// ---------------- fused edge kernel (launch #4; 2 CTAs/SM, m32xn32, fp16) ----
#define SB_W2H   0                 // 128x136 fp16 = 34816 B (W2^T)
#define SB_UH    34816             // 34816 B  u (fp16)
#define SB_W1E   69632             // 2048 fp16 = 4096 B
#define SB_W1R   73728             // 512 B
#define SB_BE2   74240             // 512 B
#define EDGE_SMEM_BYTES 74752

__global__ __launch_bounds__(512, 2) void k_edge(const float* __restrict__ x,
                                                 const float* __restrict__ ea,
                                                 const float* __restrict__ We1,
                                                 const float* __restrict__ We2,
                                                 const float* __restrict__ be2) {
    extern __shared__ char smem[];
    __half* w2h = reinterpret_cast<__half*>(smem + SB_W2H);
    __half* uhi = reinterpret_cast<__half*>(smem + SB_UH);
    __half* W1e_h = reinterpret_cast<__half*>(smem + SB_W1E);
    float* W1r_s = reinterpret_cast<float*>(smem + SB_W1R);
    float* be2_s = reinterpret_cast<float*>(smem + SB_BE2);

    const int t = threadIdx.x;
    const int w = t >> 5, lane = t & 31;

    for (int i = t; i < 16384; i += 512) {
        const int k = i >> 7, c = i & 127;
        w2h[c * BSTRIDE + k] = __float2half_rn(We2[i]);
    }
    for (int i = t; i < 2048; i += 512) W1e_h[i] = __float2half_rn(We1[257 * 128 + i]);
    if (t < 128) {
        W1r_s[t] = We1[256 * 128 + t];
        be2_s[t] = be2[t];
    }
    __syncthreads();

    const float4 wr = *reinterpret_cast<const float4*>(W1r_s + lane * 4);

    // Phase-B tiling: 16 warps -> m32 (mt2 = w&3) x n32 (nq2 = w>>2)
    const int mt2 = w & 3;
    const int nq2 = w >> 2;
    const int g   = lane >> 2;
    const int tq  = lane & 3;

    // ldmatrix lane maps
    const int rA = lane & 15;
    const int kA = (lane & 16) ? 8 : 0;
    const int rB = ((lane >> 4) & 1) * 8 + (lane & 7);
    const int kB = (lane & 8) ? 8 : 0;
    const uint32_t uhi_s = (uint32_t)__cvta_generic_to_shared(uhi);
    const uint32_t w2h_s = (uint32_t)__cvta_generic_to_shared(w2h);
    const uint32_t aoff  = (uint32_t)(((mt2 * 32 + rA) * BSTRIDE + kA) * 2);
    const uint32_t boff  = (uint32_t)(((nq2 * 32 + rB) * BSTRIDE + kB) * 2);
    const uint32_t mstep = 16 * BSTRIDE * 2;

    for (int tile = blockIdx.x; tile < NUM_ETILES; tile += EGRID) {
        const int e0 = tile * ETILE;
        __syncthreads();   // protect u buffer vs previous tile readers

        // ---- Phase A: 16 warps x 8 edges; u (fp16) -> smem
        {
            const int ebase = w * 8;
            const int co    = lane * 4;
            int r8 = 0, c8 = 0;
            float rad8 = 0.f;
            if (lane < 8) {
                const int eg = e0 + ebase + lane;
                r8 = g_row[eg];
                c8 = g_col[eg];
                const float dx = x[r8 * 3 + 0] - x[c8 * 3 + 0];
                const float dy = x[r8 * 3 + 1] - x[c8 * 3 + 1];
                const float dz = x[r8 * 3 + 2] - x[c8 * 3 + 2];
                rad8 = dx * dx + dy * dy + dz * dz;
            }
            float acc[8][4];
#pragma unroll
            for (int ii = 0; ii < 8; ii++) {
                const int r   = __shfl_sync(0xffffffffu, r8, ii);
                const int c   = __shfl_sync(0xffffffffu, c8, ii);
                const float rad = __shfl_sync(0xffffffffu, rad8, ii);
                const uint2 a2 = *reinterpret_cast<const uint2*>(g_hAB + (size_t)r * 256 + co);
                const uint2 b2 = *reinterpret_cast<const uint2*>(g_hAB + (size_t)c * 256 + 128 + co);
                const float2 a01 = __half22float2(*reinterpret_cast<const __half2*>(&a2.x));
                const float2 a23 = __half22float2(*reinterpret_cast<const __half2*>(&a2.y));
                const float2 b01 = __half22float2(*reinterpret_cast<const __half2*>(&b2.x));
                const float2 b23 = __half22float2(*reinterpret_cast<const __half2*>(&b2.y));
                acc[ii][0] = fmaf(rad, wr.x, a01.x + b01.x);
                acc[ii][1] = fmaf(rad, wr.y, a01.y + b01.y);
                acc[ii][2] = fmaf(rad, wr.z, a23.x + b23.x);
                acc[ii][3] = fmaf(rad, wr.w, a23.y + b23.y);
            }
#pragma unroll
            for (int jb = 0; jb < 4; jb++) {
                float4 wv[4];
#pragma unroll
                for (int q = 0; q < 4; q++) {
                    const uint2 u2 = *reinterpret_cast<const uint2*>(
                        W1e_h + (jb * 4 + q) * 128 + co);
                    const float2 f01 = __half22float2(*reinterpret_cast<const __half2*>(&u2.x));
                    const float2 f23 = __half22float2(*reinterpret_cast<const __half2*>(&u2.y));
                    wv[q] = make_float4(f01.x, f01.y, f23.x, f23.y);
                }
#pragma unroll
                for (int ii = 0; ii < 8; ii++) {
                    const float4 e4 = __ldcs(reinterpret_cast<const float4*>(
                        ea + (size_t)(e0 + ebase + ii) * 16 + jb * 4));
                    const float ev[4] = {e4.x, e4.y, e4.z, e4.w};
#pragma unroll
                    for (int q = 0; q < 4; q++) {
                        acc[ii][0] = fmaf(ev[q], wv[q].x, acc[ii][0]);
                        acc[ii][1] = fmaf(ev[q], wv[q].y, acc[ii][1]);
                        acc[ii][2] = fmaf(ev[q], wv[q].z, acc[ii][2]);
                        acc[ii][3] = fmaf(ev[q], wv[q].w, acc[ii][3]);
                    }
                }
            }
#pragma unroll
            for (int ii = 0; ii < 8; ii++) {
                const int e = ebase + ii;
                __half2 hp0 = __floats2half2_rn(silu_f(acc[ii][0]), silu_f(acc[ii][1]));
                __half2 hp1 = __floats2half2_rn(silu_f(acc[ii][2]), silu_f(acc[ii][3]));
                uint2 hv;
                hv.x = *reinterpret_cast<uint32_t*>(&hp0);
                hv.y = *reinterpret_cast<uint32_t*>(&hp1);
                *reinterpret_cast<uint2*>(uhi + e * BSTRIDE + co) = hv;
            }
        }
        __syncthreads();

        // ---- Phase B: D = u @ W2 (fp16 mma, m32xn32 warp tile)
        {
            float d[2][4][4];
#pragma unroll
            for (int mi = 0; mi < 2; mi++)
#pragma unroll
                for (int nt = 0; nt < 4; nt++)
#pragma unroll
                    for (int j = 0; j < 4; j++) d[mi][nt][j] = 0.f;

#pragma unroll
            for (int ks = 0; ks < 8; ks++) {
                const uint32_t kb2 = ks * 32;
                uint32_t ah[2][4], bf[2][4];
                ldsm4(ah[0], uhi_s + aoff + kb2);
                ldsm4(ah[1], uhi_s + aoff + mstep + kb2);
                ldsm4(bf[0], w2h_s + boff + kb2);
                ldsm4(bf[1], w2h_s + boff + mstep + kb2);
#pragma unroll
                for (int p = 0; p < 2; p++)
#pragma unroll
                    for (int sub = 0; sub < 2; sub++) {
                        const int nt = p * 2 + sub;
                        const uint32_t b0 = bf[p][sub * 2], b1 = bf[p][sub * 2 + 1];
#pragma unroll
                        for (int mi = 0; mi < 2; mi++)
                            mma_f16(d[mi][nt], ah[mi][0], ah[mi][1], ah[mi][2], ah[mi][3], b0, b1);
                    }
            }

            const bool evenq = (tq & 1) == 0;
#pragma unroll
            for (int mi = 0; mi < 2; mi++) {
                const int er0 = g_row[e0 + mt2 * 32 + mi * 16 + g];
                const int er1 = g_row[e0 + mt2 * 32 + mi * 16 + g + 8];
#pragma unroll
                for (int nt = 0; nt < 4; nt++) {
                    const int col = nq2 * 32 + nt * 8 + 2 * tq;
                    const float b0v = be2_s[col];
                    const float b1v = be2_s[col + 1];
                    const float v00 = silu_f(d[mi][nt][0] + b0v);
                    const float v01 = silu_f(d[mi][nt][1] + b1v);
                    const float v10 = silu_f(d[mi][nt][2] + b0v);
                    const float v11 = silu_f(d[mi][nt][3] + b1v);
                    const float p00 = __shfl_xor_sync(0xffffffffu, v00, 1);
                    const float p01 = __shfl_xor_sync(0xffffffffu, v01, 1);
                    const float p10 = __shfl_xor_sync(0xffffffffu, v10, 1);
                    const float p11 = __shfl_xor_sync(0xffffffffu, v11, 1);
                    const int colbase = nq2 * 32 + nt * 8 + (tq & 2) * 2;
                    if (evenq) {
                        asm volatile("red.global.add.v4.f32 [%0], {%1, %2, %3, %4};"
                                     :: "l"(g_agg + (size_t)er0 * 128 + colbase),
                                        "f"(v00), "f"(v01), "f"(p00), "f"(p01) : "memory");
                    } else {
                        asm volatile("red.global.add.v4.f32 [%0], {%1, %2, %3, %4};"
                                     :: "l"(g_agg + (size_t)er1 * 128 + colbase),
                                        "f"(p10), "f"(p11), "f"(v10), "f"(v11) : "memory");
                    }
                }
            }
        }
    }
}

// ---------------- k_node (launch #5; persistent fp16 mma): mid = silu(hn1 + agg@Wn1b)
// Warp tile m16 x n16; also accumulates pool (sum h) and cnt per tile.
#define NB_BH   0                  // 128x136 fp16 = 34816 B  (Wn1b^T [c][k])
#define NB_AH   34816              // 32x136 fp16 = 8704 B    (agg tile)
#define NODE_SMEM_BYTES 43520

__global__ __launch_bounds__(512, 2) void k_node(const float* __restrict__ h,
                                                 const float* __restrict__ Wn1) {
    extern __shared__ char smem[];
    __half* Bn = reinterpret_cast<__half*>(smem + NB_BH);
    __half* Ah = reinterpret_cast<__half*>(smem + NB_AH);

    const int t = threadIdx.x;
    const int w = t >> 5, lane = t & 31;

    // stage Wn1b^T fp16 once per block: Bn[c][k] = Wn1[(128+k)*128 + c]
    for (int i = t; i < 16384; i += 512) {
        const int c = i >> 7, k = i & 127;
        Bn[c * BSTRIDE + k] = __float2half_rn(Wn1[(128 + k) * 128 + c]);
    }
    __syncthreads();

    const int mt = w & 1;        // 2 m-tiles of 16 nodes
    const int nb = w >> 1;       // 8 n-tiles of 16 cols
    const int g  = lane >> 2;
    const int tq = lane & 3;

    for (int tile = blockIdx.x; tile < NUM_PTILES; tile += NGRID) {
        const int n0 = tile * 32;
        __syncthreads();
        // stage agg tile (fp32 -> fp16) and accumulate h sums + counts
        for (int idx = t; idx < 1024; idx += 512) {
            const int n = idx >> 5, kq = idx & 31;
            const int ng = n0 + n;
            float4 v = make_float4(0.f, 0.f, 0.f, 0.f);
            if (ng < N_NODES) {
                v = *reinterpret_cast<const float4*>(g_agg + (size_t)ng * 128 + kq * 4);
                const int b = g_batch[ng];
                const float4 hv = *reinterpret_cast<const float4*>(h + (size_t)ng * 128 + kq * 4);
                asm volatile("red.global.add.v4.f32 [%0], {%1, %2, %3, %4};"
                             :: "l"(g_pool + b * 128 + kq * 4),
                                "f"(hv.x), "f"(hv.y), "f"(hv.z), "f"(hv.w) : "memory");
            }
            __half2 p0 = __floats2half2_rn(v.x, v.y);
            __half2 p1 = __floats2half2_rn(v.z, v.w);
            uint2 hv2;
            hv2.x = *reinterpret_cast<uint32_t*>(&p0);
            hv2.y = *reinterpret_cast<uint32_t*>(&p1);
            *reinterpret_cast<uint2*>(Ah + n * BSTRIDE + kq * 4) = hv2;
        }
        if (t < 32 && n0 + t < N_NODES) atomicAdd(&g_cnt[g_batch[n0 + t]], 1.0f);
        __syncthreads();

        float d[2][4];
#pragma unroll
        for (int sub = 0; sub < 2; sub++)
#pragma unroll
            for (int j = 0; j < 4; j++) d[sub][j] = 0.f;

        const int arow = mt * 16 + g;
#pragma unroll
        for (int ks = 0; ks < 8; ks++) {
            const int kb = ks * 16;
            const __half* Ap = Ah + arow * BSTRIDE + 2 * tq + kb;
            const uint32_t a0 = *reinterpret_cast<const uint32_t*>(Ap);
            const uint32_t a1 = *reinterpret_cast<const uint32_t*>(Ap + 8 * BSTRIDE);
            const uint32_t a2 = *reinterpret_cast<const uint32_t*>(Ap + 8);
            const uint32_t a3 = *reinterpret_cast<const uint32_t*>(Ap + 8 * BSTRIDE + 8);
#pragma unroll
            for (int sub = 0; sub < 2; sub++) {
                const __half* Bp = Bn + (nb * 16 + sub * 8 + g) * BSTRIDE + 2 * tq + kb;
                const uint32_t b0 = *reinterpret_cast<const uint32_t*>(Bp);
                const uint32_t b1 = *reinterpret_cast<const uint32_t*>(Bp + 8);
                mma_f16(d[sub], a0, a1, a2, a3, b0, b1);
            }
        }

        // epilogue: mid = silu(d + hn1); red.v2 scatter to poolm
        const int r0 = n0 + mt * 16 + g;
        const int r1 = r0 + 8;
        const int b0i = (r0 < N_NODES) ? g_batch[r0] : 0;
        const int b1i = (r1 < N_NODES) ? g_batch[r1] : 0;
#pragma unroll
        for (int sub = 0; sub < 2; sub++) {
            const int col = nb * 16 + sub * 8 + 2 * tq;
            if (r0 < N_NODES) {
                const float2 hn = *reinterpret_cast<const float2*>(g_hn1 + (size_t)r0 * 128 + col);
                const float m0 = silu_f(d[sub][0] + hn.x);
                const float m1 = silu_f(d[sub][1] + hn.y);
                asm volatile("red.global.add.v2.f32 [%0], {%1, %2};"
                             :: "l"(g_poolm + b0i * 128 + col), "f"(m0), "f"(m1) : "memory");
            }
            if (r1 < N_NODES) {
                const float2 hn = *reinterpret_cast<const float2*>(g_hn1 + (size_t)r1 * 128 + col);
                const float m0 = silu_f(d[sub][2] + hn.x);
                const float m1 = silu_f(d[sub][3] + hn.y);
                asm volatile("red.global.add.v2.f32 [%0], {%1, %2};"
                             :: "l"(g_poolm + b1i * 128 + col), "f"(m0), "f"(m1) : "memory");
            }
        }
    }
}

// ---------------- k_pool_final (launch #6) ----------------
__global__ void k_pool_final(const float* __restrict__ Wn2,
                             const float* __restrict__ bn2,
                             float* __restrict__ out) {
    __shared__ float pm[128];
    const int g = blockIdx.x;
    const int c = threadIdx.x;
    pm[c] = g_poolm[g * 128 + c];
    __syncthreads();
    float dot = 0.f;
    for (int k = 0; k < 128; k++)
        dot = fmaf(pm[k], __ldg(Wn2 + k * 128 + c), dot);
    const float cnt = g_cnt[g];
    const float s = g_pool[g * 128 + c] + dot + cnt * __ldg(bn2 + c);
    out[g * 128 + c] = s / fmaxf(cnt, 1.0f);
}

// ---------------- launcher ----------------
extern "C" void kernel_launch(void* const* d_in, const int* in_sizes, int n_in,
                              void* d_out, int out_size) {
    const float* h   = (const float*)d_in[0];
    const void*  ei  = d_in[1];
    const float* x   = (const float*)d_in[2];
    const float* ea  = (const float*)d_in[3];
    const void*  bat = d_in[4];
    const float* We1 = (const float*)d_in[5];
    const float* be1 = (const float*)d_in[6];
    const float* We2 = (const float*)d_in[7];
    const float* be2 = (const float*)d_in[8];
    const float* Wn1 = (const float*)d_in[9];
    const float* bn1 = (const float*)d_in[10];
    const float* Wn2 = (const float*)d_in[11];
    const float* bn2 = (const float*)d_in[12];
    float* out = (float*)d_out;

    cudaFuncSetAttribute(k_pre,  cudaFuncAttributeMaxDynamicSharedMemorySize, PRE_SMEM_BYTES);
    cudaFuncSetAttribute(k_edge, cudaFuncAttributeMaxDynamicSharedMemorySize, EDGE_SMEM_BYTES);
    cudaFuncSetAttribute(k_node, cudaFuncAttributeMaxDynamicSharedMemorySize, NODE_SMEM_BYTES);

    k_init<<<(N_NODES * HID / 4 + 255) / 256, 256>>>(ei);                       // #1
    k_cvt_idx<<<(N_EDGES + 255) / 256, 256>>>(ei, bat);                         // #2
    k_pre<<<PGRID, 512, PRE_SMEM_BYTES>>>(h, We1, be1, Wn1, bn1);               // #3
    k_edge<<<EGRID, 512, EDGE_SMEM_BYTES>>>(x, ea, We1, We2, be2);              // #4 (ncu slot)
    k_node<<<NGRID, 512, NODE_SMEM_BYTES>>>(h, Wn1);                            // #5
    k_pool_final<<<N_GRAPHS, HID>>>(Wn2, bn2, out);                             // #6
}